// round 2
// baseline (speedup 1.0000x reference)
#include <cuda_runtime.h>
#include <cstdint>

#define BATCH  2
#define SEQ    2048
#define DMODEL 1024
#define NHEADS 16
#define DK     64
#define GM     (BATCH * SEQ)   // 4096 rows for all projection GEMMs

// ---------------- scratch (no cudaMalloc allowed) ----------------
__device__ float g_Qp[(size_t)GM * DMODEL];
__device__ float g_Kp[(size_t)GM * DMODEL];
__device__ float g_Vp[(size_t)GM * DMODEL];
__device__ float g_Ctx[(size_t)GM * DMODEL];

// ---------------------------------------------------------------
// C[M,N] = A[M,K] @ B[N,K]^T   (all row-major, K = N = 1024)
// 128x128 block tile, BK=16, 256 threads, 8x8 microtile.
// ---------------------------------------------------------------
__global__ __launch_bounds__(256, 2)
void gemm_abT(const float* __restrict__ A, const float* __restrict__ Bm,
              float* __restrict__ C) {
    constexpr int K = DMODEL, N = DMODEL;
    __shared__ float As[16][132];   // transposed [k][i], padded for banks+align
    __shared__ float Bs[16][132];

    const int tid = threadIdx.x;
    const int bm = blockIdx.y * 128;
    const int bn = blockIdx.x * 128;
    const int tx = tid & 15, ty = tid >> 4;
    const int lrow = tid >> 2;          // 0..63
    const int lk   = (tid & 3) * 4;     // 0,4,8,12

    float acc[8][8];
#pragma unroll
    for (int i = 0; i < 8; i++)
#pragma unroll
        for (int j = 0; j < 8; j++) acc[i][j] = 0.f;

    for (int k0 = 0; k0 < K; k0 += 16) {
#pragma unroll
        for (int half = 0; half < 2; half++) {
            const int r = lrow + half * 64;
            float4 av = *(const float4*)&A[(size_t)(bm + r) * K + k0 + lk];
            As[lk + 0][r] = av.x; As[lk + 1][r] = av.y;
            As[lk + 2][r] = av.z; As[lk + 3][r] = av.w;
            float4 bv = *(const float4*)&Bm[(size_t)(bn + r) * K + k0 + lk];
            Bs[lk + 0][r] = bv.x; Bs[lk + 1][r] = bv.y;
            Bs[lk + 2][r] = bv.z; Bs[lk + 3][r] = bv.w;
        }
        __syncthreads();
#pragma unroll
        for (int k = 0; k < 16; k++) {
            float a[8], b[8];
            *(float4*)(a)     = *(const float4*)&As[k][ty * 8];
            *(float4*)(a + 4) = *(const float4*)&As[k][ty * 8 + 4];
            *(float4*)(b)     = *(const float4*)&Bs[k][tx * 8];
            *(float4*)(b + 4) = *(const float4*)&Bs[k][tx * 8 + 4];
#pragma unroll
            for (int i = 0; i < 8; i++)
#pragma unroll
                for (int j = 0; j < 8; j++)
                    acc[i][j] += a[i] * b[j];
        }
        __syncthreads();
    }
#pragma unroll
    for (int i = 0; i < 8; i++) {
        float* crow = &C[(size_t)(bm + ty * 8 + i) * N + bn + tx * 8];
        *(float4*)&crow[0] = make_float4(acc[i][0], acc[i][1], acc[i][2], acc[i][3]);
        *(float4*)&crow[4] = make_float4(acc[i][4], acc[i][5], acc[i][6], acc[i][7]);
    }
}

// ---------------------------------------------------------------
// Flash-style attention, fp32. One thread per query row.
// Block = 128 query rows of one (batch, head). Chunks of 64 keys.
// q is pre-scaled by 1/sqrt(DK).
// mask is a 4-byte-per-element tensor (bool widened by harness to int32 or
// float32): NONZERO bits -> masked -> additive -1e9 penalty.
// ---------------------------------------------------------------
__global__ __launch_bounds__(128, 2)
void flash_attn(const float* __restrict__ Qp, const float* __restrict__ Kp,
                const float* __restrict__ Vp, const uint32_t* __restrict__ mask,
                float* __restrict__ Ctx) {
    extern __shared__ float sm[];
    float (*Ks)[68] = (float(*)[68])sm;                 // 64 x 68
    float (*Vs)[68] = (float(*)[68])(sm + 64 * 68);     // 64 x 68
    float (*Ss)[65] = (float(*)[65])(sm + 2 * 64 * 68); // 128 x 65 (per-thread row)

    const int b = blockIdx.z, h = blockIdx.y;
    const int tid = threadIdx.x;
    const int m = blockIdx.x * 128 + tid;

    float q[64];
    {
        const float* qrow = &Qp[((size_t)b * SEQ + m) * DMODEL + h * DK];
#pragma unroll
        for (int d = 0; d < 64; d += 4) {
            float4 v4 = *(const float4*)&qrow[d];
            q[d] = v4.x * 0.125f; q[d + 1] = v4.y * 0.125f;
            q[d + 2] = v4.z * 0.125f; q[d + 3] = v4.w * 0.125f;
        }
    }
    float acc[64];
#pragma unroll
    for (int d = 0; d < 64; d++) acc[d] = 0.f;
    float mmax = -3.0e38f, l = 0.f;

    const uint32_t* mrow = &mask[((size_t)b * SEQ + m) * SEQ];
    const int lr = tid >> 1;            // 0..63
    const int lc = (tid & 1) * 32;      // 0 / 32

    for (int n0 = 0; n0 < SEQ; n0 += 64) {
        __syncthreads();   // previous chunk fully consumed
        {
            const float* ksrc = &Kp[((size_t)b * SEQ + n0 + lr) * DMODEL + h * DK + lc];
            const float* vsrc = &Vp[((size_t)b * SEQ + n0 + lr) * DMODEL + h * DK + lc];
#pragma unroll
            for (int c = 0; c < 32; c += 4) {
                *(float4*)&Ks[lr][lc + c] = *(const float4*)&ksrc[c];
                *(float4*)&Vs[lr][lc + c] = *(const float4*)&vsrc[c];
            }
        }
        __syncthreads();

        // mask words -> additive penalty staged in this thread's Ss row
#pragma unroll
        for (int w = 0; w < 16; w++) {
            uint4 mv = *(const uint4*)(mrow + n0 + w * 4);
            Ss[tid][w * 4 + 0] = mv.x ? -1e9f : 0.f;
            Ss[tid][w * 4 + 1] = mv.y ? -1e9f : 0.f;
            Ss[tid][w * 4 + 2] = mv.z ? -1e9f : 0.f;
            Ss[tid][w * 4 + 3] = mv.w ? -1e9f : 0.f;
        }

        // scores for this chunk
        float cm = -3.0e38f;
#pragma unroll 8
        for (int kk = 0; kk < 64; kk++) {
            const float* kr = Ks[kk];
            float d0 = 0.f, d1 = 0.f, d2 = 0.f, d3 = 0.f;
#pragma unroll
            for (int d = 0; d < 64; d += 4) {
                d0 += q[d]     * kr[d];
                d1 += q[d + 1] * kr[d + 1];
                d2 += q[d + 2] * kr[d + 2];
                d3 += q[d + 3] * kr[d + 3];
            }
            float s = (d0 + d1) + (d2 + d3) + Ss[tid][kk];
            Ss[tid][kk] = s;
            cm = fmaxf(cm, s);
        }

        const float mnew = fmaxf(mmax, cm);
        const float corr = __expf(mmax - mnew);
        l *= corr;
#pragma unroll
        for (int d = 0; d < 64; d++) acc[d] *= corr;

#pragma unroll 4
        for (int kk = 0; kk < 64; kk++) {
            float p = __expf(Ss[tid][kk] - mnew);
            l += p;
            const float* vr = Vs[kk];
#pragma unroll
            for (int d = 0; d < 64; d++) acc[d] += p * vr[d];
        }
        mmax = mnew;
    }

    const float inv = 1.f / l;
    float* orow = &Ctx[((size_t)b * SEQ + m) * DMODEL + h * DK];
#pragma unroll
    for (int d = 0; d < 64; d += 4)
        *(float4*)&orow[d] =
            make_float4(acc[d] * inv, acc[d + 1] * inv, acc[d + 2] * inv, acc[d + 3] * inv);
}

// ---------------------------------------------------------------
extern "C" void kernel_launch(void* const* d_in, const int* in_sizes, int n_in,
                              void* d_out, int out_size) {
    const float*    q    = (const float*)d_in[0];
    const float*    k    = (const float*)d_in[1];
    const float*    v    = (const float*)d_in[2];
    const uint32_t* mask = (const uint32_t*)d_in[3];
    const float*    Wq   = (const float*)d_in[4];
    const float*    Wk   = (const float*)d_in[5];
    const float*    Wv   = (const float*)d_in[6];
    const float*    Wo   = (const float*)d_in[7];
    float* out = (float*)d_out;

    float *Qp, *Kp, *Vp, *Ctx;
    cudaGetSymbolAddress((void**)&Qp,  g_Qp);
    cudaGetSymbolAddress((void**)&Kp,  g_Kp);
    cudaGetSymbolAddress((void**)&Vp,  g_Vp);
    cudaGetSymbolAddress((void**)&Ctx, g_Ctx);

    dim3 gg(DMODEL / 128, GM / 128);   // (8, 32)
    gemm_abT<<<gg, 256>>>(q, Wq, Qp);
    gemm_abT<<<gg, 256>>>(k, Wk, Kp);
    gemm_abT<<<gg, 256>>>(v, Wv, Vp);

    const int smem = (2 * 64 * 68 + 128 * 65) * (int)sizeof(float);  // 68,096 B
    cudaFuncSetAttribute(flash_attn, cudaFuncAttributeMaxDynamicSharedMemorySize, smem);
    dim3 ga(SEQ / 128, NHEADS, BATCH);  // (16, 16, 2)
    flash_attn<<<ga, 128, smem>>>(Qp, Kp, Vp, mask, Ctx);

    gemm_abT<<<gg, 256>>>(Ctx, Wo, out);
}

// round 4
// speedup vs baseline: 1.1746x; 1.1746x over previous
#include <cuda_runtime.h>
#include <cuda_bf16.h>
#include <cstdint>

#define BATCH  2
#define SEQ    2048
#define DMODEL 1024
#define NHEADS 16
#define DK     64
#define GM     (BATCH * SEQ)   // 4096 rows for all projection GEMMs

// ---------------- scratch (no cudaMalloc allowed) ----------------
__device__ float g_Qp[(size_t)GM * DMODEL];
__device__ float g_Kp[(size_t)GM * DMODEL];
__device__ float g_Vp[(size_t)GM * DMODEL];
__device__ float g_Ctx[(size_t)GM * DMODEL];

// ======================= mma.sync GEMM =======================
// C[M,N] = A[M,K] @ B[N,K]^T  (row-major, K = N = 1024)
// 128x128 CTA tile, 8 warps (2x4), warp tile 64x32, K-chunk 64.
// fp32 inputs are split in-kernel into hi/lo bf16; 3 MMA passes:
// hi*hi + lo*hi + hi*lo  ->  ~fp32 accuracy with tensor-core rate.

#define LDMATRIX_X4(r0, r1, r2, r3, addr)                                   \
    asm volatile("ldmatrix.sync.aligned.m8n8.x4.shared.b16 {%0,%1,%2,%3}, [%4];" \
                 : "=r"(r0), "=r"(r1), "=r"(r2), "=r"(r3) : "r"(addr))

#define MMA16816(d, a, b0, b1)                                              \
    asm volatile("mma.sync.aligned.m16n8k16.row.col.f32.bf16.bf16.f32 "     \
                 "{%0,%1,%2,%3}, {%4,%5,%6,%7}, {%8,%9}, {%0,%1,%2,%3};"    \
                 : "+f"((d)[0]), "+f"((d)[1]), "+f"((d)[2]), "+f"((d)[3])   \
                 : "r"((a)[0]), "r"((a)[1]), "r"((a)[2]), "r"((a)[3]),      \
                   "r"(b0), "r"(b1))

__device__ __forceinline__ uint32_t smem_u32(const void* p) {
    uint32_t a;
    asm("{ .reg .u64 t; cvta.to.shared.u64 t, %1; cvt.u32.u64 %0, t; }" : "=r"(a) : "l"(p));
    return a;
}

__device__ __forceinline__ void split4(float4 v, uint2& h, uint2& l) {
    __nv_bfloat16 hx = __float2bfloat16(v.x), hy = __float2bfloat16(v.y);
    __nv_bfloat16 hz = __float2bfloat16(v.z), hw = __float2bfloat16(v.w);
    __nv_bfloat16 lx = __float2bfloat16(v.x - __bfloat162float(hx));
    __nv_bfloat16 ly = __float2bfloat16(v.y - __bfloat162float(hy));
    __nv_bfloat16 lz = __float2bfloat16(v.z - __bfloat162float(hz));
    __nv_bfloat16 lw = __float2bfloat16(v.w - __bfloat162float(hw));
    __nv_bfloat162 h0 = __halves2bfloat162(hx, hy), h1 = __halves2bfloat162(hz, hw);
    __nv_bfloat162 l0 = __halves2bfloat162(lx, ly), l1 = __halves2bfloat162(lz, lw);
    h.x = *(uint32_t*)&h0; h.y = *(uint32_t*)&h1;
    l.x = *(uint32_t*)&l0; l.y = *(uint32_t*)&l1;
}

// smem: 4 tiles of 128 rows x 72 bf16 (144B padded rows) = 73728 B
#define ROWB   144
#define OFF_AH 0
#define OFF_AL 18432
#define OFF_BH 36864
#define OFF_BL 55296
#define GEMM_SMEM 73728

__global__ __launch_bounds__(256, 2)
void gemm_mma(const float* __restrict__ A, const float* __restrict__ Bm,
              float* __restrict__ C) {
    extern __shared__ __align__(16) char smem[];
    constexpr int K = DMODEL, N = DMODEL;

    const int tid = threadIdx.x;
    const int lane = tid & 31, wid = tid >> 5;
    const int warp_m = wid >> 2;          // 0..1  (64 rows each)
    const int warp_n = wid & 3;           // 0..3  (32 cols each)
    const int bm = blockIdx.y * 128;
    const int bn = blockIdx.x * 128;
    const uint32_t sb = smem_u32(smem);

    // global load assignment: row = tid>>1 (0..127), half = 32 cols
    const int lrow = tid >> 1;
    const int lhalf = (tid & 1) * 32;

    // ldmatrix per-lane address components
    const int a_row = warp_m * 64 + (lane & 15);
    const uint32_t a_off = (uint32_t)(lane >> 4) * 16;               // k-half byte off
    const int b_row = warp_n * 32 + (lane & 7) + ((lane >> 4) & 1) * 8;
    const uint32_t b_off = (uint32_t)((lane >> 3) & 1) * 16;

    float acc[4][4][4];
#pragma unroll
    for (int mt = 0; mt < 4; mt++)
#pragma unroll
        for (int nt = 0; nt < 4; nt++)
#pragma unroll
            for (int r = 0; r < 4; r++) acc[mt][nt][r] = 0.f;

    for (int k0 = 0; k0 < K; k0 += 64) {
        __syncthreads();
        // ---- load + split fp32 -> hi/lo bf16 tiles ----
        {
            const float4* ga = (const float4*)&A[(size_t)(bm + lrow) * K + k0 + lhalf];
            const float4* gb = (const float4*)&Bm[(size_t)(bn + lrow) * K + k0 + lhalf];
            char* pAH = smem + OFF_AH + lrow * ROWB + lhalf * 2;
            char* pAL = smem + OFF_AL + lrow * ROWB + lhalf * 2;
            char* pBH = smem + OFF_BH + lrow * ROWB + lhalf * 2;
            char* pBL = smem + OFF_BL + lrow * ROWB + lhalf * 2;
#pragma unroll
            for (int i = 0; i < 8; i++) {
                uint2 h, l;
                split4(ga[i], h, l);
                *(uint2*)(pAH + i * 8) = h;
                *(uint2*)(pAL + i * 8) = l;
                split4(gb[i], h, l);
                *(uint2*)(pBH + i * 8) = h;
                *(uint2*)(pBL + i * 8) = l;
            }
        }
        __syncthreads();

        // ---- compute: 4 k-steps of 16 ----
#pragma unroll
        for (int ks = 0; ks < 4; ks++) {
            uint32_t ah[4][4], al[4][4], bb[2][4];
#pragma unroll
            for (int mt = 0; mt < 4; mt++) {
                const uint32_t ra = (uint32_t)(a_row + mt * 16) * ROWB + (uint32_t)ks * 32 + a_off;
                LDMATRIX_X4(ah[mt][0], ah[mt][1], ah[mt][2], ah[mt][3], sb + OFF_AH + ra);
                LDMATRIX_X4(al[mt][0], al[mt][1], al[mt][2], al[mt][3], sb + OFF_AL + ra);
            }
#pragma unroll
            for (int nt2 = 0; nt2 < 2; nt2++) {
                const uint32_t rb = (uint32_t)(b_row + nt2 * 16) * ROWB + (uint32_t)ks * 32 + b_off;
                LDMATRIX_X4(bb[nt2][0], bb[nt2][1], bb[nt2][2], bb[nt2][3], sb + OFF_BH + rb);
            }
#pragma unroll
            for (int mt = 0; mt < 4; mt++)
#pragma unroll
                for (int nt = 0; nt < 4; nt++) {
                    const uint32_t b0 = bb[nt >> 1][(nt & 1) * 2];
                    const uint32_t b1 = bb[nt >> 1][(nt & 1) * 2 + 1];
                    MMA16816(acc[mt][nt], ah[mt], b0, b1);
                    MMA16816(acc[mt][nt], al[mt], b0, b1);
                }
#pragma unroll
            for (int nt2 = 0; nt2 < 2; nt2++) {
                const uint32_t rb = (uint32_t)(b_row + nt2 * 16) * ROWB + (uint32_t)ks * 32 + b_off;
                LDMATRIX_X4(bb[nt2][0], bb[nt2][1], bb[nt2][2], bb[nt2][3], sb + OFF_BL + rb);
            }
#pragma unroll
            for (int mt = 0; mt < 4; mt++)
#pragma unroll
                for (int nt = 0; nt < 4; nt++) {
                    const uint32_t b0 = bb[nt >> 1][(nt & 1) * 2];
                    const uint32_t b1 = bb[nt >> 1][(nt & 1) * 2 + 1];
                    MMA16816(acc[mt][nt], ah[mt], b0, b1);
                }
        }
    }

    // ---- epilogue: fragment -> global ----
    const int erow = bm + warp_m * 64 + (lane >> 2);
    const int ecol = bn + warp_n * 32 + (lane & 3) * 2;
#pragma unroll
    for (int mt = 0; mt < 4; mt++)
#pragma unroll
        for (int nt = 0; nt < 4; nt++) {
            float* c0 = &C[(size_t)(erow + mt * 16) * N + ecol + nt * 8];
            float* c1 = &C[(size_t)(erow + mt * 16 + 8) * N + ecol + nt * 8];
            *(float2*)c0 = make_float2(acc[mt][nt][0], acc[mt][nt][1]);
            *(float2*)c1 = make_float2(acc[mt][nt][2], acc[mt][nt][3]);
        }
}

// ---------------------------------------------------------------
// Flash-style attention, fp32. One thread per query row. (validated R2)
// ---------------------------------------------------------------
__global__ __launch_bounds__(128, 2)
void flash_attn(const float* __restrict__ Qp, const float* __restrict__ Kp,
                const float* __restrict__ Vp, const uint32_t* __restrict__ mask,
                float* __restrict__ Ctx) {
    extern __shared__ float sm[];
    float (*Ks)[68] = (float(*)[68])sm;                 // 64 x 68
    float (*Vs)[68] = (float(*)[68])(sm + 64 * 68);     // 64 x 68
    float (*Ss)[65] = (float(*)[65])(sm + 2 * 64 * 68); // 128 x 65

    const int b = blockIdx.z, h = blockIdx.y;
    const int tid = threadIdx.x;
    const int m = blockIdx.x * 128 + tid;

    float q[64];
    {
        const float* qrow = &Qp[((size_t)b * SEQ + m) * DMODEL + h * DK];
#pragma unroll
        for (int d = 0; d < 64; d += 4) {
            float4 v4 = *(const float4*)&qrow[d];
            q[d] = v4.x * 0.125f; q[d + 1] = v4.y * 0.125f;
            q[d + 2] = v4.z * 0.125f; q[d + 3] = v4.w * 0.125f;
        }
    }
    float acc[64];
#pragma unroll
    for (int d = 0; d < 64; d++) acc[d] = 0.f;
    float mmax = -3.0e38f, l = 0.f;

    const uint32_t* mrow = &mask[((size_t)b * SEQ + m) * SEQ];
    const int lr = tid >> 1;
    const int lc = (tid & 1) * 32;

    for (int n0 = 0; n0 < SEQ; n0 += 64) {
        __syncthreads();
        {
            const float* ksrc = &Kp[((size_t)b * SEQ + n0 + lr) * DMODEL + h * DK + lc];
            const float* vsrc = &Vp[((size_t)b * SEQ + n0 + lr) * DMODEL + h * DK + lc];
#pragma unroll
            for (int c = 0; c < 32; c += 4) {
                *(float4*)&Ks[lr][lc + c] = *(const float4*)&ksrc[c];
                *(float4*)&Vs[lr][lc + c] = *(const float4*)&vsrc[c];
            }
        }
        __syncthreads();

#pragma unroll
        for (int w = 0; w < 16; w++) {
            uint4 mv = *(const uint4*)(mrow + n0 + w * 4);
            Ss[tid][w * 4 + 0] = mv.x ? -1e9f : 0.f;
            Ss[tid][w * 4 + 1] = mv.y ? -1e9f : 0.f;
            Ss[tid][w * 4 + 2] = mv.z ? -1e9f : 0.f;
            Ss[tid][w * 4 + 3] = mv.w ? -1e9f : 0.f;
        }

        float cm = -3.0e38f;
#pragma unroll 8
        for (int kk = 0; kk < 64; kk++) {
            const float* kr = Ks[kk];
            float d0 = 0.f, d1 = 0.f, d2 = 0.f, d3 = 0.f;
#pragma unroll
            for (int d = 0; d < 64; d += 4) {
                d0 += q[d]     * kr[d];
                d1 += q[d + 1] * kr[d + 1];
                d2 += q[d + 2] * kr[d + 2];
                d3 += q[d + 3] * kr[d + 3];
            }
            float s = (d0 + d1) + (d2 + d3) + Ss[tid][kk];
            Ss[tid][kk] = s;
            cm = fmaxf(cm, s);
        }

        const float mnew = fmaxf(mmax, cm);
        const float corr = __expf(mmax - mnew);
        l *= corr;
#pragma unroll
        for (int d = 0; d < 64; d++) acc[d] *= corr;

#pragma unroll 4
        for (int kk = 0; kk < 64; kk++) {
            float p = __expf(Ss[tid][kk] - mnew);
            l += p;
            const float* vr = Vs[kk];
#pragma unroll
            for (int d = 0; d < 64; d++) acc[d] += p * vr[d];
        }
        mmax = mnew;
    }

    const float inv = 1.f / l;
    float* orow = &Ctx[((size_t)b * SEQ + m) * DMODEL + h * DK];
#pragma unroll
    for (int d = 0; d < 64; d += 4)
        *(float4*)&orow[d] =
            make_float4(acc[d] * inv, acc[d + 1] * inv, acc[d + 2] * inv, acc[d + 3] * inv);
}

// ---------------------------------------------------------------
extern "C" void kernel_launch(void* const* d_in, const int* in_sizes, int n_in,
                              void* d_out, int out_size) {
    const float*    q    = (const float*)d_in[0];
    const float*    k    = (const float*)d_in[1];
    const float*    v    = (const float*)d_in[2];
    const uint32_t* mask = (const uint32_t*)d_in[3];
    const float*    Wq   = (const float*)d_in[4];
    const float*    Wk   = (const float*)d_in[5];
    const float*    Wv   = (const float*)d_in[6];
    const float*    Wo   = (const float*)d_in[7];
    float* out = (float*)d_out;

    float *Qp, *Kp, *Vp, *Ctx;
    cudaGetSymbolAddress((void**)&Qp,  g_Qp);
    cudaGetSymbolAddress((void**)&Kp,  g_Kp);
    cudaGetSymbolAddress((void**)&Vp,  g_Vp);
    cudaGetSymbolAddress((void**)&Ctx, g_Ctx);

    cudaFuncSetAttribute(gemm_mma, cudaFuncAttributeMaxDynamicSharedMemorySize, GEMM_SMEM);
    dim3 gg(DMODEL / 128, GM / 128);   // (8, 32)
    gemm_mma<<<gg, 256, GEMM_SMEM>>>(q, Wq, Qp);
    gemm_mma<<<gg, 256, GEMM_SMEM>>>(k, Wk, Kp);
    gemm_mma<<<gg, 256, GEMM_SMEM>>>(v, Wv, Vp);

    const int attn_smem = (2 * 64 * 68 + 128 * 65) * (int)sizeof(float);  // 68,096
    cudaFuncSetAttribute(flash_attn, cudaFuncAttributeMaxDynamicSharedMemorySize, attn_smem);
    dim3 ga(SEQ / 128, NHEADS, BATCH);  // (16, 16, 2)
    flash_attn<<<ga, 128, attn_smem>>>(Qp, Kp, Vp, mask, Ctx);

    gemm_mma<<<gg, 256, GEMM_SMEM>>>(Ctx, Wo, out);
}

// round 9
// speedup vs baseline: 2.4481x; 2.0841x over previous
#include <cuda_runtime.h>
#include <cuda_bf16.h>
#include <cstdint>

#define BATCH  2
#define SEQ    2048
#define DMODEL 1024
#define NHEADS 16
#define DK     64
#define GM     (BATCH * SEQ)

// ---------------- scratch (no cudaMalloc allowed) ----------------
__device__ float g_Qp[(size_t)GM * DMODEL];
__device__ float g_Kp[(size_t)GM * DMODEL];
__device__ float g_Vp[(size_t)GM * DMODEL];
__device__ float g_Ctx[(size_t)GM * DMODEL];
__device__ uint32_t g_mpk[(size_t)BATCH * SEQ * (SEQ / 32)];  // 1-bit packed mask

// ======================= common helpers =======================
#define LDMATRIX_X4(r0, r1, r2, r3, addr)                                   \
    asm volatile("ldmatrix.sync.aligned.m8n8.x4.shared.b16 {%0,%1,%2,%3}, [%4];" \
                 : "=r"(r0), "=r"(r1), "=r"(r2), "=r"(r3) : "r"(addr))

#define MMA16816(d, a, b0, b1)                                              \
    asm volatile("mma.sync.aligned.m16n8k16.row.col.f32.bf16.bf16.f32 "     \
                 "{%0,%1,%2,%3}, {%4,%5,%6,%7}, {%8,%9}, {%0,%1,%2,%3};"    \
                 : "+f"((d)[0]), "+f"((d)[1]), "+f"((d)[2]), "+f"((d)[3])   \
                 : "r"((a)[0]), "r"((a)[1]), "r"((a)[2]), "r"((a)[3]),      \
                   "r"(b0), "r"(b1))

__device__ __forceinline__ uint32_t smem_u32(const void* p) {
    uint32_t a;
    asm("{ .reg .u64 t; cvta.to.shared.u64 t, %1; cvt.u32.u64 %0, t; }" : "=r"(a) : "l"(p));
    return a;
}

__device__ __forceinline__ void split4(float4 v, uint2& h, uint2& l) {
    __nv_bfloat16 hx = __float2bfloat16(v.x), hy = __float2bfloat16(v.y);
    __nv_bfloat16 hz = __float2bfloat16(v.z), hw = __float2bfloat16(v.w);
    __nv_bfloat16 lx = __float2bfloat16(v.x - __bfloat162float(hx));
    __nv_bfloat16 ly = __float2bfloat16(v.y - __bfloat162float(hy));
    __nv_bfloat16 lz = __float2bfloat16(v.z - __bfloat162float(hz));
    __nv_bfloat16 lw = __float2bfloat16(v.w - __bfloat162float(hw));
    __nv_bfloat162 h0 = __halves2bfloat162(hx, hy), h1 = __halves2bfloat162(hz, hw);
    __nv_bfloat162 l0 = __halves2bfloat162(lx, ly), l1 = __halves2bfloat162(lz, lw);
    h.x = *(uint32_t*)&h0; h.y = *(uint32_t*)&h1;
    l.x = *(uint32_t*)&l0; l.y = *(uint32_t*)&l1;
}

// pack two fp32 -> bf16x2 (lo = a, hi = b)
__device__ __forceinline__ uint32_t pack2(float a, float b) {
    uint32_t r;
    asm("cvt.rn.bf16x2.f32 %0, %1, %2;" : "=r"(r) : "f"(b), "f"(a));
    return r;
}

// ======================= mma.sync GEMM (validated R4) =======================
#define ROWB   144
#define OFF_AH 0
#define OFF_AL 18432
#define OFF_BH 36864
#define OFF_BL 55296
#define GEMM_SMEM 73728

__global__ __launch_bounds__(256, 2)
void gemm_mma(const float* __restrict__ A, const float* __restrict__ Bm,
              float* __restrict__ C) {
    extern __shared__ __align__(16) char smem[];
    constexpr int K = DMODEL, N = DMODEL;

    const int tid = threadIdx.x;
    const int lane = tid & 31, wid = tid >> 5;
    const int warp_m = wid >> 2;
    const int warp_n = wid & 3;
    const int bm = blockIdx.y * 128;
    const int bn = blockIdx.x * 128;
    const uint32_t sb = smem_u32(smem);

    const int lrow = tid >> 1;
    const int lhalf = (tid & 1) * 32;

    const int a_row = warp_m * 64 + (lane & 15);
    const uint32_t a_off = (uint32_t)(lane >> 4) * 16;
    const int b_row = warp_n * 32 + (lane & 7) + ((lane >> 4) & 1) * 8;
    const uint32_t b_off = (uint32_t)((lane >> 3) & 1) * 16;

    float acc[4][4][4];
#pragma unroll
    for (int mt = 0; mt < 4; mt++)
#pragma unroll
        for (int nt = 0; nt < 4; nt++)
#pragma unroll
            for (int r = 0; r < 4; r++) acc[mt][nt][r] = 0.f;

    for (int k0 = 0; k0 < K; k0 += 64) {
        __syncthreads();
        {
            const float4* ga = (const float4*)&A[(size_t)(bm + lrow) * K + k0 + lhalf];
            const float4* gb = (const float4*)&Bm[(size_t)(bn + lrow) * K + k0 + lhalf];
            char* pAH = smem + OFF_AH + lrow * ROWB + lhalf * 2;
            char* pAL = smem + OFF_AL + lrow * ROWB + lhalf * 2;
            char* pBH = smem + OFF_BH + lrow * ROWB + lhalf * 2;
            char* pBL = smem + OFF_BL + lrow * ROWB + lhalf * 2;
#pragma unroll
            for (int i = 0; i < 8; i++) {
                uint2 h, l;
                split4(ga[i], h, l);
                *(uint2*)(pAH + i * 8) = h;
                *(uint2*)(pAL + i * 8) = l;
                split4(gb[i], h, l);
                *(uint2*)(pBH + i * 8) = h;
                *(uint2*)(pBL + i * 8) = l;
            }
        }
        __syncthreads();

#pragma unroll
        for (int ks = 0; ks < 4; ks++) {
            uint32_t ah[4][4], al[4][4], bb[2][4];
#pragma unroll
            for (int mt = 0; mt < 4; mt++) {
                const uint32_t ra = (uint32_t)(a_row + mt * 16) * ROWB + (uint32_t)ks * 32 + a_off;
                LDMATRIX_X4(ah[mt][0], ah[mt][1], ah[mt][2], ah[mt][3], sb + OFF_AH + ra);
                LDMATRIX_X4(al[mt][0], al[mt][1], al[mt][2], al[mt][3], sb + OFF_AL + ra);
            }
#pragma unroll
            for (int nt2 = 0; nt2 < 2; nt2++) {
                const uint32_t rb = (uint32_t)(b_row + nt2 * 16) * ROWB + (uint32_t)ks * 32 + b_off;
                LDMATRIX_X4(bb[nt2][0], bb[nt2][1], bb[nt2][2], bb[nt2][3], sb + OFF_BH + rb);
            }
#pragma unroll
            for (int mt = 0; mt < 4; mt++)
#pragma unroll
                for (int nt = 0; nt < 4; nt++) {
                    const uint32_t b0 = bb[nt >> 1][(nt & 1) * 2];
                    const uint32_t b1 = bb[nt >> 1][(nt & 1) * 2 + 1];
                    MMA16816(acc[mt][nt], ah[mt], b0, b1);
                    MMA16816(acc[mt][nt], al[mt], b0, b1);
                }
#pragma unroll
            for (int nt2 = 0; nt2 < 2; nt2++) {
                const uint32_t rb = (uint32_t)(b_row + nt2 * 16) * ROWB + (uint32_t)ks * 32 + b_off;
                LDMATRIX_X4(bb[nt2][0], bb[nt2][1], bb[nt2][2], bb[nt2][3], sb + OFF_BL + rb);
            }
#pragma unroll
            for (int mt = 0; mt < 4; mt++)
#pragma unroll
                for (int nt = 0; nt < 4; nt++) {
                    const uint32_t b0 = bb[nt >> 1][(nt & 1) * 2];
                    const uint32_t b1 = bb[nt >> 1][(nt & 1) * 2 + 1];
                    MMA16816(acc[mt][nt], ah[mt], b0, b1);
                }
        }
    }

    const int erow = bm + warp_m * 64 + (lane >> 2);
    const int ecol = bn + warp_n * 32 + (lane & 3) * 2;
#pragma unroll
    for (int mt = 0; mt < 4; mt++)
#pragma unroll
        for (int nt = 0; nt < 4; nt++) {
            float* c0 = &C[(size_t)(erow + mt * 16) * N + ecol + nt * 8];
            float* c1 = &C[(size_t)(erow + mt * 16 + 8) * N + ecol + nt * 8];
            *(float2*)c0 = make_float2(acc[mt][nt][0], acc[mt][nt][1]);
            *(float2*)c1 = make_float2(acc[mt][nt][2], acc[mt][nt][3]);
        }
}

// ======================= mask bit-pack =======================
// 8192 warps total; each warp packs 1024 mask words -> 32 output words.
__global__ __launch_bounds__(256)
void mask_pack(const uint32_t* __restrict__ m, uint32_t* __restrict__ out) {
    const int gwarp = (blockIdx.x * blockDim.x + threadIdx.x) >> 5;
    const int lane = threadIdx.x & 31;
    const uint32_t* base = m + (size_t)gwarp * 1024;
    uint32_t my = 0;
#pragma unroll 4
    for (int g = 0; g < 32; g++) {
        uint32_t v = base[g * 32 + lane];
        uint32_t bal = __ballot_sync(0xffffffffu, v != 0);
        if (lane == g) my = bal;
    }
    out[(size_t)gwarp * 32 + lane] = my;
}

// ======================= tensor-core flash attention =======================
// CTA: 128 query rows of one (b,h); 8 warps x 16 rows; 64-key chunks.
// Q,K,P,V all hi/lo bf16 split (3 mma passes each) -> ~fp32 accuracy.
#define AT_KH 0
#define AT_KL 9216
#define AT_VH 18432
#define AT_VL 27648
#define AT_QH 0
#define AT_QL 18432

__global__ __launch_bounds__(256)
void flash_mma(const float* __restrict__ Qp, const float* __restrict__ Kp,
               const float* __restrict__ Vp, const uint32_t* __restrict__ mpk,
               float* __restrict__ Ctx) {
    __shared__ __align__(16) char smem[36864];
    const int b = blockIdx.z, h = blockIdx.y;
    const int tid = threadIdx.x, lane = tid & 31, wid = tid >> 5;
    const int bm = blockIdx.x * 128;
    const uint32_t sb = smem_u32(smem);

    // ---- stage Q (scaled by 1/8), split hi/lo ----
    {
        const int row = tid >> 1;
        const int half = (tid & 1) * 32;
        const float4* qsrc = (const float4*)&Qp[((size_t)b * SEQ + bm + row) * DMODEL + h * DK + half];
        char* pH = smem + AT_QH + row * ROWB + half * 2;
        char* pL = smem + AT_QL + row * ROWB + half * 2;
#pragma unroll
        for (int i = 0; i < 8; i++) {
            float4 v = qsrc[i];
            v.x *= 0.125f; v.y *= 0.125f; v.z *= 0.125f; v.w *= 0.125f;
            uint2 hh, ll;
            split4(v, hh, ll);
            *(uint2*)(pH + i * 8) = hh;
            *(uint2*)(pL + i * 8) = ll;
        }
    }
    __syncthreads();

    uint32_t qh[4][4], ql[4][4];
    {
        const int a_row = wid * 16 + (lane & 15);
        const uint32_t a_off = (uint32_t)(lane >> 4) * 16;
#pragma unroll
        for (int ks = 0; ks < 4; ks++) {
            const uint32_t ra = (uint32_t)a_row * ROWB + (uint32_t)ks * 32 + a_off;
            LDMATRIX_X4(qh[ks][0], qh[ks][1], qh[ks][2], qh[ks][3], sb + AT_QH + ra);
            LDMATRIX_X4(ql[ks][0], ql[ks][1], ql[ks][2], ql[ks][3], sb + AT_QL + ra);
        }
    }

    float o[8][4];
#pragma unroll
    for (int nt = 0; nt < 8; nt++)
#pragma unroll
        for (int r = 0; r < 4; r++) o[nt][r] = 0.f;
    float m0 = -3.0e38f, m1 = -3.0e38f, l0 = 0.f, l1 = 0.f;

    const int r0 = bm + wid * 16 + (lane >> 2);
    const uint32_t* mrow0 = &mpk[((size_t)b * SEQ + r0) * (SEQ / 32)];
    const uint32_t* mrow1 = mrow0 + 8 * (SEQ / 32);

    const int b_row = (lane & 7) + ((lane >> 4) & 1) * 8;
    const uint32_t b_off = (uint32_t)((lane >> 3) & 1) * 16;
    const int colbase = (lane & 3) * 2;

    for (int c = 0; c < SEQ / 64; c++) {
        const int n0 = c * 64;
        __syncthreads();
        // ---- stage K chunk (rows) and V chunk (transposed), hi/lo ----
        {
            const int row = tid >> 2;           // 0..63 (key)
            const int qtr = (tid & 3) * 16;     // 16-col group
            const float4* ksrc = (const float4*)&Kp[((size_t)b * SEQ + n0 + row) * DMODEL + h * DK + qtr];
            const float4* vsrc = (const float4*)&Vp[((size_t)b * SEQ + n0 + row) * DMODEL + h * DK + qtr];
            char* pKH = smem + AT_KH + row * ROWB + qtr * 2;
            char* pKL = smem + AT_KL + row * ROWB + qtr * 2;
#pragma unroll
            for (int i = 0; i < 4; i++) {
                uint2 hh, ll;
                split4(ksrc[i], hh, ll);
                *(uint2*)(pKH + i * 8) = hh;
                *(uint2*)(pKL + i * 8) = ll;
                float4 vv = vsrc[i];
                const float vf[4] = {vv.x, vv.y, vv.z, vv.w};
#pragma unroll
                for (int j = 0; j < 4; j++) {
                    const int d = qtr + i * 4 + j;
                    __nv_bfloat16 vh = __float2bfloat16(vf[j]);
                    __nv_bfloat16 vl = __float2bfloat16(vf[j] - __bfloat162float(vh));
                    *(__nv_bfloat16*)(smem + AT_VH + d * ROWB + row * 2) = vh;
                    *(__nv_bfloat16*)(smem + AT_VL + d * ROWB + row * 2) = vl;
                }
            }
        }
        __syncthreads();

        // ---- S = Q K^T (3 passes) ----
        float s[8][4];
#pragma unroll
        for (int nt = 0; nt < 8; nt++)
#pragma unroll
            for (int r = 0; r < 4; r++) s[nt][r] = 0.f;

#pragma unroll
        for (int ks = 0; ks < 4; ks++) {
#pragma unroll
            for (int nt2 = 0; nt2 < 4; nt2++) {
                uint32_t kh[4], kl[4];
                const uint32_t rb = (uint32_t)(b_row + nt2 * 16) * ROWB + (uint32_t)ks * 32 + b_off;
                LDMATRIX_X4(kh[0], kh[1], kh[2], kh[3], sb + AT_KH + rb);
                LDMATRIX_X4(kl[0], kl[1], kl[2], kl[3], sb + AT_KL + rb);
#pragma unroll
                for (int j = 0; j < 2; j++) {
                    const int nt = nt2 * 2 + j;
                    MMA16816(s[nt], qh[ks], kh[j * 2], kh[j * 2 + 1]);
                    MMA16816(s[nt], ql[ks], kh[j * 2], kh[j * 2 + 1]);
                    MMA16816(s[nt], qh[ks], kl[j * 2], kl[j * 2 + 1]);
                }
            }
        }

        // ---- mask ----
        {
            const uint64_t mk0 = (uint64_t)mrow0[c * 2] | ((uint64_t)mrow0[c * 2 + 1] << 32);
            const uint64_t mk1 = (uint64_t)mrow1[c * 2] | ((uint64_t)mrow1[c * 2 + 1] << 32);
#pragma unroll
            for (int nt = 0; nt < 8; nt++) {
                const int col = nt * 8 + colbase;
                s[nt][0] += ((mk0 >> col) & 1) ? -1e9f : 0.f;
                s[nt][1] += ((mk0 >> (col + 1)) & 1) ? -1e9f : 0.f;
                s[nt][2] += ((mk1 >> col) & 1) ? -1e9f : 0.f;
                s[nt][3] += ((mk1 >> (col + 1)) & 1) ? -1e9f : 0.f;
            }
        }

        // ---- online softmax ----
        float cm0 = -3.0e38f, cm1 = -3.0e38f;
#pragma unroll
        for (int nt = 0; nt < 8; nt++) {
            cm0 = fmaxf(cm0, fmaxf(s[nt][0], s[nt][1]));
            cm1 = fmaxf(cm1, fmaxf(s[nt][2], s[nt][3]));
        }
        cm0 = fmaxf(cm0, __shfl_xor_sync(0xffffffffu, cm0, 1));
        cm0 = fmaxf(cm0, __shfl_xor_sync(0xffffffffu, cm0, 2));
        cm1 = fmaxf(cm1, __shfl_xor_sync(0xffffffffu, cm1, 1));
        cm1 = fmaxf(cm1, __shfl_xor_sync(0xffffffffu, cm1, 2));

        const float mn0 = fmaxf(m0, cm0), mn1 = fmaxf(m1, cm1);
        const float sc0 = __expf(m0 - mn0), sc1 = __expf(m1 - mn1);
        l0 *= sc0; l1 *= sc1;
#pragma unroll
        for (int nt = 0; nt < 8; nt++) {
            o[nt][0] *= sc0; o[nt][1] *= sc0;
            o[nt][2] *= sc1; o[nt][3] *= sc1;
        }
        m0 = mn0; m1 = mn1;

        uint32_t aPh[4][4], aPl[4][4];
#pragma unroll
        for (int nt = 0; nt < 8; nt++) {
            float p0 = __expf(s[nt][0] - mn0);
            float p1 = __expf(s[nt][1] - mn0);
            float p2 = __expf(s[nt][2] - mn1);
            float p3 = __expf(s[nt][3] - mn1);
            l0 += p0 + p1; l1 += p2 + p3;
            const int t = nt >> 1, jj = (nt & 1) * 2;
            uint32_t hp01 = pack2(p0, p1), hp23 = pack2(p2, p3);
            __nv_bfloat162 hb01 = *(__nv_bfloat162*)&hp01;
            __nv_bfloat162 hb23 = *(__nv_bfloat162*)&hp23;
            uint32_t lp01 = pack2(p0 - __bfloat162float(hb01.x), p1 - __bfloat162float(hb01.y));
            uint32_t lp23 = pack2(p2 - __bfloat162float(hb23.x), p3 - __bfloat162float(hb23.y));
            aPh[t][jj] = hp01; aPh[t][jj + 1] = hp23;
            aPl[t][jj] = lp01; aPl[t][jj + 1] = lp23;
        }

        // ---- O += P V (3 passes) ----
#pragma unroll
        for (int t = 0; t < 4; t++) {          // key group (k dim)
#pragma unroll
            for (int nt2 = 0; nt2 < 4; nt2++) { // d group
                uint32_t vh[4], vl[4];
                const uint32_t rb = (uint32_t)(b_row + nt2 * 16) * ROWB + (uint32_t)t * 32 + b_off;
                LDMATRIX_X4(vh[0], vh[1], vh[2], vh[3], sb + AT_VH + rb);
                LDMATRIX_X4(vl[0], vl[1], vl[2], vl[3], sb + AT_VL + rb);
#pragma unroll
                for (int j = 0; j < 2; j++) {
                    const int nt = nt2 * 2 + j;
                    MMA16816(o[nt], aPh[t], vh[j * 2], vh[j * 2 + 1]);
                    MMA16816(o[nt], aPl[t], vh[j * 2], vh[j * 2 + 1]);
                    MMA16816(o[nt], aPh[t], vl[j * 2], vl[j * 2 + 1]);
                }
            }
        }
    }

    // ---- epilogue ----
    l0 += __shfl_xor_sync(0xffffffffu, l0, 1);
    l0 += __shfl_xor_sync(0xffffffffu, l0, 2);
    l1 += __shfl_xor_sync(0xffffffffu, l1, 1);
    l1 += __shfl_xor_sync(0xffffffffu, l1, 2);
    const float inv0 = 1.f / l0, inv1 = 1.f / l1;

    const int ecol = h * DK + (lane & 3) * 2;
    float* out0 = &Ctx[((size_t)b * SEQ + r0) * DMODEL + ecol];
    float* out1 = &Ctx[((size_t)b * SEQ + r0 + 8) * DMODEL + ecol];
#pragma unroll
    for (int nt = 0; nt < 8; nt++) {
        *(float2*)(out0 + nt * 8) = make_float2(o[nt][0] * inv0, o[nt][1] * inv0);
        *(float2*)(out1 + nt * 8) = make_float2(o[nt][2] * inv1, o[nt][3] * inv1);
    }
}

// ---------------------------------------------------------------
extern "C" void kernel_launch(void* const* d_in, const int* in_sizes, int n_in,
                              void* d_out, int out_size) {
    const float*    q    = (const float*)d_in[0];
    const float*    k    = (const float*)d_in[1];
    const float*    v    = (const float*)d_in[2];
    const uint32_t* mask = (const uint32_t*)d_in[3];
    const float*    Wq   = (const float*)d_in[4];
    const float*    Wk   = (const float*)d_in[5];
    const float*    Wv   = (const float*)d_in[6];
    const float*    Wo   = (const float*)d_in[7];
    float* out = (float*)d_out;

    float *Qp, *Kp, *Vp, *Ctx;
    uint32_t* mpk;
    cudaGetSymbolAddress((void**)&Qp,  g_Qp);
    cudaGetSymbolAddress((void**)&Kp,  g_Kp);
    cudaGetSymbolAddress((void**)&Vp,  g_Vp);
    cudaGetSymbolAddress((void**)&Ctx, g_Ctx);
    cudaGetSymbolAddress((void**)&mpk, g_mpk);

    cudaFuncSetAttribute(gemm_mma, cudaFuncAttributeMaxDynamicSharedMemorySize, GEMM_SMEM);
    dim3 gg(DMODEL / 128, GM / 128);   // (8, 32)

    // 8192 warps needed -> 1024 blocks of 256 threads (8 warps each)
    mask_pack<<<1024, 256>>>(mask, mpk);
    gemm_mma<<<gg, 256, GEMM_SMEM>>>(q, Wq, Qp);
    gemm_mma<<<gg, 256, GEMM_SMEM>>>(k, Wk, Kp);
    gemm_mma<<<gg, 256, GEMM_SMEM>>>(v, Wv, Vp);

    dim3 ga(SEQ / 128, NHEADS, BATCH);  // (16, 16, 2)
    flash_mma<<<ga, 256>>>(Qp, Kp, Vp, mpk, Ctx);

    gemm_mma<<<gg, 256, GEMM_SMEM>>>(Ctx, Wo, out);
}

// round 11
// speedup vs baseline: 2.8231x; 1.1532x over previous
#include <cuda_runtime.h>
#include <cuda_bf16.h>
#include <cstdint>

#define BATCH  2
#define SEQ    2048
#define DMODEL 1024
#define NHEADS 16
#define DK     64
#define GM     (BATCH * SEQ)
#define DD     (DMODEL * DMODEL)

// ---------------- scratch (no cudaMalloc allowed) ----------------
__device__ float g_QKVp[(size_t)3 * GM * DMODEL];
__device__ float g_Ctx[(size_t)GM * DMODEL];
__device__ __nv_bfloat16 g_AH[(size_t)3 * GM * DMODEL];
__device__ __nv_bfloat16 g_AL[(size_t)3 * GM * DMODEL];
__device__ __nv_bfloat16 g_WH[(size_t)4 * DD];
__device__ __nv_bfloat16 g_WL[(size_t)4 * DD];
__device__ uint32_t g_mpk[(size_t)BATCH * SEQ * (SEQ / 32)];

// ======================= common helpers =======================
#define LDMATRIX_X4(r0, r1, r2, r3, addr)                                   \
    asm volatile("ldmatrix.sync.aligned.m8n8.x4.shared.b16 {%0,%1,%2,%3}, [%4];" \
                 : "=r"(r0), "=r"(r1), "=r"(r2), "=r"(r3) : "r"(addr))

#define MMA16816(d, a, b0, b1)                                              \
    asm volatile("mma.sync.aligned.m16n8k16.row.col.f32.bf16.bf16.f32 "     \
                 "{%0,%1,%2,%3}, {%4,%5,%6,%7}, {%8,%9}, {%0,%1,%2,%3};"    \
                 : "+f"((d)[0]), "+f"((d)[1]), "+f"((d)[2]), "+f"((d)[3])   \
                 : "r"((a)[0]), "r"((a)[1]), "r"((a)[2]), "r"((a)[3]),      \
                   "r"(b0), "r"(b1))

__device__ __forceinline__ uint32_t smem_u32(const void* p) {
    uint32_t a;
    asm("{ .reg .u64 t; cvta.to.shared.u64 t, %1; cvt.u32.u64 %0, t; }" : "=r"(a) : "l"(p));
    return a;
}

__device__ __forceinline__ void cpa16(uint32_t saddr, const void* g) {
    asm volatile("cp.async.cg.shared.global [%0], [%1], 16;" :: "r"(saddr), "l"(g));
}
#define CPA_COMMIT() asm volatile("cp.async.commit_group;" ::: "memory")
#define CPA_WAIT1()  asm volatile("cp.async.wait_group 1;" ::: "memory")
#define CPA_WAIT0()  asm volatile("cp.async.wait_group 0;" ::: "memory")

__device__ __forceinline__ void split4(float4 v, uint2& h, uint2& l) {
    __nv_bfloat16 hx = __float2bfloat16(v.x), hy = __float2bfloat16(v.y);
    __nv_bfloat16 hz = __float2bfloat16(v.z), hw = __float2bfloat16(v.w);
    __nv_bfloat16 lx = __float2bfloat16(v.x - __bfloat162float(hx));
    __nv_bfloat16 ly = __float2bfloat16(v.y - __bfloat162float(hy));
    __nv_bfloat16 lz = __float2bfloat16(v.z - __bfloat162float(hz));
    __nv_bfloat16 lw = __float2bfloat16(v.w - __bfloat162float(hw));
    __nv_bfloat162 h0 = __halves2bfloat162(hx, hy), h1 = __halves2bfloat162(hz, hw);
    __nv_bfloat162 l0 = __halves2bfloat162(lx, ly), l1 = __halves2bfloat162(lz, lw);
    h.x = *(uint32_t*)&h0; h.y = *(uint32_t*)&h1;
    l.x = *(uint32_t*)&l0; l.y = *(uint32_t*)&l1;
}

__device__ __forceinline__ uint32_t pack2(float a, float b) {
    uint32_t r;
    asm("cvt.rn.bf16x2.f32 %0, %1, %2;" : "=r"(r) : "f"(b), "f"(a));
    return r;
}

// ======================= presplit: fp32 -> hi/lo bf16 =======================
__global__ __launch_bounds__(256)
void presplit(const float* __restrict__ in, __nv_bfloat16* __restrict__ hi,
              __nv_bfloat16* __restrict__ lo) {
    const int i = blockIdx.x * blockDim.x + threadIdx.x;
    float4 v = ((const float4*)in)[i];
    uint2 h, l;
    split4(v, h, l);
    ((uint2*)hi)[i] = h;
    ((uint2*)lo)[i] = l;
}

// ======================= pipelined hi/lo mma GEMM =======================
// C[M,N] = A[M,K] @ W[N,K]^T ; CTA tile 128x256, warp tile 64x64 (2x4 warps),
// K-chunk 32, 2-stage cp.async. W selected per 32 grid.y blocks (QKV batch).
#define ROWS   80               // padded row stride (32 bf16 data + pad)
#define ST_AH  0
#define ST_AL  10240
#define ST_BH  20480
#define ST_BL  40960
#define STAGE  61440
#define GEMM_SMEM (2 * STAGE)   // 122880

__global__ __launch_bounds__(256, 1)
void gemm_pipe(const __nv_bfloat16* __restrict__ Ah, const __nv_bfloat16* __restrict__ Al,
               const __nv_bfloat16* __restrict__ Wh, const __nv_bfloat16* __restrict__ Wl,
               float* __restrict__ C) {
    extern __shared__ __align__(16) char smem[];
    constexpr int K = DMODEL, N = DMODEL, NC = K / 32;

    const int tid = threadIdx.x;
    const int lane = tid & 31, wid = tid >> 5;
    const int warp_m = wid >> 2;          // 0..1 (64 rows)
    const int warp_n = wid & 3;           // 0..3 (64 cols)
    const int bm = blockIdx.y * 128;
    const int bn = blockIdx.x * 256;
    const int third = blockIdx.y >> 5;    // W select for batched QKV (0 when grid.y<=32)
    const __nv_bfloat16* WhS = Wh + (size_t)third * DD;
    const __nv_bfloat16* WlS = Wl + (size_t)third * DD;
    const uint32_t sb = smem_u32(smem);

    const int lrow = tid >> 2;            // load row helper
    const int lc = (tid & 3) * 16;        // byte chunk in 64B row

    // cp.async issue for one stage
    auto issue = [&](int buf, int k0) {
        const uint32_t st = sb + buf * STAGE;
#pragma unroll
        for (int j = 0; j < 2; j++) {       // A: 128 rows hi + lo
            const int row = lrow + j * 64;
            const size_t g = (size_t)(bm + row) * K + k0 + (lc >> 1);
            cpa16(st + ST_AH + row * ROWS + lc, Ah + g);
            cpa16(st + ST_AL + row * ROWS + lc, Al + g);
        }
#pragma unroll
        for (int j = 0; j < 4; j++) {       // B: 256 rows hi + lo
            const int row = lrow + j * 64;
            const size_t g = (size_t)(bn + row) * K + k0 + (lc >> 1);
            cpa16(st + ST_BH + row * ROWS + lc, WhS + g);
            cpa16(st + ST_BL + row * ROWS + lc, WlS + g);
        }
    };

    float acc[4][8][4];
#pragma unroll
    for (int mt = 0; mt < 4; mt++)
#pragma unroll
        for (int nt = 0; nt < 8; nt++)
#pragma unroll
            for (int r = 0; r < 4; r++) acc[mt][nt][r] = 0.f;

    const int a_row = warp_m * 64 + (lane & 15);
    const uint32_t a_half = (uint32_t)(lane >> 4) * 16;
    const int b_row = warp_n * 64 + (lane & 7) + ((lane >> 4) & 1) * 8;
    const uint32_t b_half = (uint32_t)((lane >> 3) & 1) * 16;

    issue(0, 0);
    CPA_COMMIT();

    for (int c = 0; c < NC; c++) {
        if (c + 1 < NC) {
            issue((c + 1) & 1, (c + 1) * 32);
            CPA_COMMIT();
            CPA_WAIT1();
        } else {
            CPA_WAIT0();
        }
        __syncthreads();

        const uint32_t st = sb + (c & 1) * STAGE;
#pragma unroll
        for (int ks = 0; ks < 2; ks++) {
            const uint32_t koff = (uint32_t)ks * 32;
            uint32_t ah[4][4], al[4][4];
#pragma unroll
            for (int mt = 0; mt < 4; mt++) {
                const uint32_t ra = (uint32_t)(a_row + mt * 16) * ROWS + koff + a_half;
                LDMATRIX_X4(ah[mt][0], ah[mt][1], ah[mt][2], ah[mt][3], st + ST_AH + ra);
                LDMATRIX_X4(al[mt][0], al[mt][1], al[mt][2], al[mt][3], st + ST_AL + ra);
            }
#pragma unroll
            for (int nt2 = 0; nt2 < 4; nt2++) {
                uint32_t bh[4], bl[4];
                const uint32_t rb = (uint32_t)(b_row + nt2 * 16) * ROWS + koff + b_half;
                LDMATRIX_X4(bh[0], bh[1], bh[2], bh[3], st + ST_BH + rb);
                LDMATRIX_X4(bl[0], bl[1], bl[2], bl[3], st + ST_BL + rb);
#pragma unroll
                for (int j = 0; j < 2; j++) {
                    const int nt = nt2 * 2 + j;
#pragma unroll
                    for (int mt = 0; mt < 4; mt++) {
                        MMA16816(acc[mt][nt], ah[mt], bh[j * 2], bh[j * 2 + 1]);
                        MMA16816(acc[mt][nt], al[mt], bh[j * 2], bh[j * 2 + 1]);
                        MMA16816(acc[mt][nt], ah[mt], bl[j * 2], bl[j * 2 + 1]);
                    }
                }
            }
        }
        __syncthreads();
    }

    // epilogue
    const int erow = bm + warp_m * 64 + (lane >> 2);
    const int ecol = bn + warp_n * 64 + (lane & 3) * 2;
#pragma unroll
    for (int mt = 0; mt < 4; mt++)
#pragma unroll
        for (int nt = 0; nt < 8; nt++) {
            float* c0 = &C[(size_t)(erow + mt * 16) * N + ecol + nt * 8];
            float* c1 = &C[(size_t)(erow + mt * 16 + 8) * N + ecol + nt * 8];
            *(float2*)c0 = make_float2(acc[mt][nt][0], acc[mt][nt][1]);
            *(float2*)c1 = make_float2(acc[mt][nt][2], acc[mt][nt][3]);
        }
}

// ======================= mask bit-pack (validated R7) =======================
__global__ __launch_bounds__(256)
void mask_pack(const uint32_t* __restrict__ m, uint32_t* __restrict__ out) {
    const int gwarp = (blockIdx.x * blockDim.x + threadIdx.x) >> 5;
    const int lane = threadIdx.x & 31;
    const uint32_t* base = m + (size_t)gwarp * 1024;
    uint32_t my = 0;
#pragma unroll 4
    for (int g = 0; g < 32; g++) {
        uint32_t v = base[g * 32 + lane];
        uint32_t bal = __ballot_sync(0xffffffffu, v != 0);
        if (lane == g) my = bal;
    }
    out[(size_t)gwarp * 32 + lane] = my;
}

// ======================= tensor-core flash attention (validated R7) =======================
#define ROWB   144
#define AT_KH 0
#define AT_KL 9216
#define AT_VH 18432
#define AT_VL 27648
#define AT_QH 0
#define AT_QL 18432

__global__ __launch_bounds__(256)
void flash_mma(const float* __restrict__ Qp, const float* __restrict__ Kp,
               const float* __restrict__ Vp, const uint32_t* __restrict__ mpk,
               float* __restrict__ Ctx) {
    __shared__ __align__(16) char smem[36864];
    const int b = blockIdx.z, h = blockIdx.y;
    const int tid = threadIdx.x, lane = tid & 31, wid = tid >> 5;
    const int bm = blockIdx.x * 128;
    const uint32_t sb = smem_u32(smem);

    {
        const int row = tid >> 1;
        const int half = (tid & 1) * 32;
        const float4* qsrc = (const float4*)&Qp[((size_t)b * SEQ + bm + row) * DMODEL + h * DK + half];
        char* pH = smem + AT_QH + row * ROWB + half * 2;
        char* pL = smem + AT_QL + row * ROWB + half * 2;
#pragma unroll
        for (int i = 0; i < 8; i++) {
            float4 v = qsrc[i];
            v.x *= 0.125f; v.y *= 0.125f; v.z *= 0.125f; v.w *= 0.125f;
            uint2 hh, ll;
            split4(v, hh, ll);
            *(uint2*)(pH + i * 8) = hh;
            *(uint2*)(pL + i * 8) = ll;
        }
    }
    __syncthreads();

    uint32_t qh[4][4], ql[4][4];
    {
        const int a_row = wid * 16 + (lane & 15);
        const uint32_t a_off = (uint32_t)(lane >> 4) * 16;
#pragma unroll
        for (int ks = 0; ks < 4; ks++) {
            const uint32_t ra = (uint32_t)a_row * ROWB + (uint32_t)ks * 32 + a_off;
            LDMATRIX_X4(qh[ks][0], qh[ks][1], qh[ks][2], qh[ks][3], sb + AT_QH + ra);
            LDMATRIX_X4(ql[ks][0], ql[ks][1], ql[ks][2], ql[ks][3], sb + AT_QL + ra);
        }
    }

    float o[8][4];
#pragma unroll
    for (int nt = 0; nt < 8; nt++)
#pragma unroll
        for (int r = 0; r < 4; r++) o[nt][r] = 0.f;
    float m0 = -3.0e38f, m1 = -3.0e38f, l0 = 0.f, l1 = 0.f;

    const int r0 = bm + wid * 16 + (lane >> 2);
    const uint32_t* mrow0 = &mpk[((size_t)b * SEQ + r0) * (SEQ / 32)];
    const uint32_t* mrow1 = mrow0 + 8 * (SEQ / 32);

    const int b_row = (lane & 7) + ((lane >> 4) & 1) * 8;
    const uint32_t b_off = (uint32_t)((lane >> 3) & 1) * 16;
    const int colbase = (lane & 3) * 2;

    for (int c = 0; c < SEQ / 64; c++) {
        const int n0 = c * 64;
        __syncthreads();
        {
            const int row = tid >> 2;
            const int qtr = (tid & 3) * 16;
            const float4* ksrc = (const float4*)&Kp[((size_t)b * SEQ + n0 + row) * DMODEL + h * DK + qtr];
            const float4* vsrc = (const float4*)&Vp[((size_t)b * SEQ + n0 + row) * DMODEL + h * DK + qtr];
            char* pKH = smem + AT_KH + row * ROWB + qtr * 2;
            char* pKL = smem + AT_KL + row * ROWB + qtr * 2;
#pragma unroll
            for (int i = 0; i < 4; i++) {
                uint2 hh, ll;
                split4(ksrc[i], hh, ll);
                *(uint2*)(pKH + i * 8) = hh;
                *(uint2*)(pKL + i * 8) = ll;
                float4 vv = vsrc[i];
                const float vf[4] = {vv.x, vv.y, vv.z, vv.w};
#pragma unroll
                for (int j = 0; j < 4; j++) {
                    const int d = qtr + i * 4 + j;
                    __nv_bfloat16 vh = __float2bfloat16(vf[j]);
                    __nv_bfloat16 vl = __float2bfloat16(vf[j] - __bfloat162float(vh));
                    *(__nv_bfloat16*)(smem + AT_VH + d * ROWB + row * 2) = vh;
                    *(__nv_bfloat16*)(smem + AT_VL + d * ROWB + row * 2) = vl;
                }
            }
        }
        __syncthreads();

        float s[8][4];
#pragma unroll
        for (int nt = 0; nt < 8; nt++)
#pragma unroll
            for (int r = 0; r < 4; r++) s[nt][r] = 0.f;

#pragma unroll
        for (int ks = 0; ks < 4; ks++) {
#pragma unroll
            for (int nt2 = 0; nt2 < 4; nt2++) {
                uint32_t kh[4], kl[4];
                const uint32_t rb = (uint32_t)(b_row + nt2 * 16) * ROWB + (uint32_t)ks * 32 + b_off;
                LDMATRIX_X4(kh[0], kh[1], kh[2], kh[3], sb + AT_KH + rb);
                LDMATRIX_X4(kl[0], kl[1], kl[2], kl[3], sb + AT_KL + rb);
#pragma unroll
                for (int j = 0; j < 2; j++) {
                    const int nt = nt2 * 2 + j;
                    MMA16816(s[nt], qh[ks], kh[j * 2], kh[j * 2 + 1]);
                    MMA16816(s[nt], ql[ks], kh[j * 2], kh[j * 2 + 1]);
                    MMA16816(s[nt], qh[ks], kl[j * 2], kl[j * 2 + 1]);
                }
            }
        }

        {
            const uint64_t mk0 = (uint64_t)mrow0[c * 2] | ((uint64_t)mrow0[c * 2 + 1] << 32);
            const uint64_t mk1 = (uint64_t)mrow1[c * 2] | ((uint64_t)mrow1[c * 2 + 1] << 32);
#pragma unroll
            for (int nt = 0; nt < 8; nt++) {
                const int col = nt * 8 + colbase;
                s[nt][0] += ((mk0 >> col) & 1) ? -1e9f : 0.f;
                s[nt][1] += ((mk0 >> (col + 1)) & 1) ? -1e9f : 0.f;
                s[nt][2] += ((mk1 >> col) & 1) ? -1e9f : 0.f;
                s[nt][3] += ((mk1 >> (col + 1)) & 1) ? -1e9f : 0.f;
            }
        }

        float cm0 = -3.0e38f, cm1 = -3.0e38f;
#pragma unroll
        for (int nt = 0; nt < 8; nt++) {
            cm0 = fmaxf(cm0, fmaxf(s[nt][0], s[nt][1]));
            cm1 = fmaxf(cm1, fmaxf(s[nt][2], s[nt][3]));
        }
        cm0 = fmaxf(cm0, __shfl_xor_sync(0xffffffffu, cm0, 1));
        cm0 = fmaxf(cm0, __shfl_xor_sync(0xffffffffu, cm0, 2));
        cm1 = fmaxf(cm1, __shfl_xor_sync(0xffffffffu, cm1, 1));
        cm1 = fmaxf(cm1, __shfl_xor_sync(0xffffffffu, cm1, 2));

        const float mn0 = fmaxf(m0, cm0), mn1 = fmaxf(m1, cm1);
        const float sc0 = __expf(m0 - mn0), sc1 = __expf(m1 - mn1);
        l0 *= sc0; l1 *= sc1;
#pragma unroll
        for (int nt = 0; nt < 8; nt++) {
            o[nt][0] *= sc0; o[nt][1] *= sc0;
            o[nt][2] *= sc1; o[nt][3] *= sc1;
        }
        m0 = mn0; m1 = mn1;

        uint32_t aPh[4][4], aPl[4][4];
#pragma unroll
        for (int nt = 0; nt < 8; nt++) {
            float p0 = __expf(s[nt][0] - mn0);
            float p1 = __expf(s[nt][1] - mn0);
            float p2 = __expf(s[nt][2] - mn1);
            float p3 = __expf(s[nt][3] - mn1);
            l0 += p0 + p1; l1 += p2 + p3;
            const int t = nt >> 1, jj = (nt & 1) * 2;
            uint32_t hp01 = pack2(p0, p1), hp23 = pack2(p2, p3);
            __nv_bfloat162 hb01 = *(__nv_bfloat162*)&hp01;
            __nv_bfloat162 hb23 = *(__nv_bfloat162*)&hp23;
            uint32_t lp01 = pack2(p0 - __bfloat162float(hb01.x), p1 - __bfloat162float(hb01.y));
            uint32_t lp23 = pack2(p2 - __bfloat162float(hb23.x), p3 - __bfloat162float(hb23.y));
            aPh[t][jj] = hp01; aPh[t][jj + 1] = hp23;
            aPl[t][jj] = lp01; aPl[t][jj + 1] = lp23;
        }

#pragma unroll
        for (int t = 0; t < 4; t++) {
#pragma unroll
            for (int nt2 = 0; nt2 < 4; nt2++) {
                uint32_t vh[4], vl[4];
                const uint32_t rb = (uint32_t)(b_row + nt2 * 16) * ROWB + (uint32_t)t * 32 + b_off;
                LDMATRIX_X4(vh[0], vh[1], vh[2], vh[3], sb + AT_VH + rb);
                LDMATRIX_X4(vl[0], vl[1], vl[2], vl[3], sb + AT_VL + rb);
#pragma unroll
                for (int j = 0; j < 2; j++) {
                    const int nt = nt2 * 2 + j;
                    MMA16816(o[nt], aPh[t], vh[j * 2], vh[j * 2 + 1]);
                    MMA16816(o[nt], aPl[t], vh[j * 2], vh[j * 2 + 1]);
                    MMA16816(o[nt], aPh[t], vl[j * 2], vl[j * 2 + 1]);
                }
            }
        }
    }

    l0 += __shfl_xor_sync(0xffffffffu, l0, 1);
    l0 += __shfl_xor_sync(0xffffffffu, l0, 2);
    l1 += __shfl_xor_sync(0xffffffffu, l1, 1);
    l1 += __shfl_xor_sync(0xffffffffu, l1, 2);
    const float inv0 = 1.f / l0, inv1 = 1.f / l1;

    const int ecol = h * DK + (lane & 3) * 2;
    float* out0 = &Ctx[((size_t)b * SEQ + r0) * DMODEL + ecol];
    float* out1 = &Ctx[((size_t)b * SEQ + r0 + 8) * DMODEL + ecol];
#pragma unroll
    for (int nt = 0; nt < 8; nt++) {
        *(float2*)(out0 + nt * 8) = make_float2(o[nt][0] * inv0, o[nt][1] * inv0);
        *(float2*)(out1 + nt * 8) = make_float2(o[nt][2] * inv1, o[nt][3] * inv1);
    }
}

// ---------------------------------------------------------------
extern "C" void kernel_launch(void* const* d_in, const int* in_sizes, int n_in,
                              void* d_out, int out_size) {
    const float*    q    = (const float*)d_in[0];
    const float*    k    = (const float*)d_in[1];
    const float*    v    = (const float*)d_in[2];
    const uint32_t* mask = (const uint32_t*)d_in[3];
    const float*    Wq   = (const float*)d_in[4];
    const float*    Wk   = (const float*)d_in[5];
    const float*    Wv   = (const float*)d_in[6];
    const float*    Wo   = (const float*)d_in[7];
    float* out = (float*)d_out;

    float *QKVp, *Ctx;
    __nv_bfloat16 *AH, *AL, *WH, *WL;
    uint32_t* mpk;
    cudaGetSymbolAddress((void**)&QKVp, g_QKVp);
    cudaGetSymbolAddress((void**)&Ctx,  g_Ctx);
    cudaGetSymbolAddress((void**)&AH,   g_AH);
    cudaGetSymbolAddress((void**)&AL,   g_AL);
    cudaGetSymbolAddress((void**)&WH,   g_WH);
    cudaGetSymbolAddress((void**)&WL,   g_WL);
    cudaGetSymbolAddress((void**)&mpk,  g_mpk);

    cudaFuncSetAttribute(gemm_pipe, cudaFuncAttributeMaxDynamicSharedMemorySize, GEMM_SMEM);

    const size_t AD = (size_t)GM * DMODEL;
    const int gA = (int)(AD / 4 / 256);   // 4096 blocks per activation tensor
    const int gW = DD / 4 / 256;          // 1024 blocks per weight

    // pre-split activations + weights
    presplit<<<gA, 256>>>(q, AH, AL);
    presplit<<<gA, 256>>>(k, AH + AD, AL + AD);
    presplit<<<gA, 256>>>(v, AH + 2 * AD, AL + 2 * AD);
    presplit<<<gW, 256>>>(Wq, WH, WL);
    presplit<<<gW, 256>>>(Wk, WH + DD, WL + DD);
    presplit<<<gW, 256>>>(Wv, WH + 2 * DD, WL + 2 * DD);
    presplit<<<gW, 256>>>(Wo, WH + 3 * DD, WL + 3 * DD);
    mask_pack<<<1024, 256>>>(mask, mpk);

    // batched Q/K/V projections: grid.y = 96, third = y>>5 selects W
    dim3 gqkv(DMODEL / 256, 3 * GM / 128);  // (4, 96)
    gemm_pipe<<<gqkv, 256, GEMM_SMEM>>>(AH, AL, WH, WL, QKVp);

    dim3 ga(SEQ / 128, NHEADS, BATCH);
    flash_mma<<<ga, 256>>>(QKVp, QKVp + AD, QKVp + 2 * AD, mpk, Ctx);

    // output projection
    presplit<<<gA, 256>>>(Ctx, AH, AL);
    dim3 go(DMODEL / 256, GM / 128);        // (4, 32)
    gemm_pipe<<<go, 256, GEMM_SMEM>>>(AH, AL, WH + 3 * DD, WL + 3 * DD, out);
}

// round 14
// speedup vs baseline: 3.1315x; 1.1093x over previous
#include <cuda_runtime.h>
#include <cuda_bf16.h>
#include <cstdint>

#define BATCH  2
#define SEQ    2048
#define DMODEL 1024
#define NHEADS 16
#define DK     64
#define GM     (BATCH * SEQ)
#define DD     (DMODEL * DMODEL)

// ---------------- scratch (no cudaMalloc allowed) ----------------
__device__ float g_QKVp[(size_t)3 * GM * DMODEL];
__device__ float g_Ctx[(size_t)GM * DMODEL];
__device__ __nv_bfloat16 g_AH[(size_t)3 * GM * DMODEL];
__device__ __nv_bfloat16 g_AL[(size_t)3 * GM * DMODEL];
__device__ __nv_bfloat16 g_WH[(size_t)4 * DD];
__device__ __nv_bfloat16 g_WL[(size_t)4 * DD];
__device__ uint32_t g_mpk[(size_t)BATCH * SEQ * (SEQ / 32)];

// ======================= common helpers =======================
#define LDMATRIX_X4(r0, r1, r2, r3, addr)                                   \
    asm volatile("ldmatrix.sync.aligned.m8n8.x4.shared.b16 {%0,%1,%2,%3}, [%4];" \
                 : "=r"(r0), "=r"(r1), "=r"(r2), "=r"(r3) : "r"(addr))

#define LDMATRIX_X4_T(r0, r1, r2, r3, addr)                                 \
    asm volatile("ldmatrix.sync.aligned.m8n8.x4.trans.shared.b16 {%0,%1,%2,%3}, [%4];" \
                 : "=r"(r0), "=r"(r1), "=r"(r2), "=r"(r3) : "r"(addr))

#define MMA16816(d, a, b0, b1)                                              \
    asm volatile("mma.sync.aligned.m16n8k16.row.col.f32.bf16.bf16.f32 "     \
                 "{%0,%1,%2,%3}, {%4,%5,%6,%7}, {%8,%9}, {%0,%1,%2,%3};"    \
                 : "+f"((d)[0]), "+f"((d)[1]), "+f"((d)[2]), "+f"((d)[3])   \
                 : "r"((a)[0]), "r"((a)[1]), "r"((a)[2]), "r"((a)[3]),      \
                   "r"(b0), "r"(b1))

__device__ __forceinline__ uint32_t smem_u32(const void* p) {
    uint32_t a;
    asm("{ .reg .u64 t; cvta.to.shared.u64 t, %1; cvt.u32.u64 %0, t; }" : "=r"(a) : "l"(p));
    return a;
}

__device__ __forceinline__ void cpa16(uint32_t saddr, const void* g) {
    asm volatile("cp.async.cg.shared.global [%0], [%1], 16;" :: "r"(saddr), "l"(g));
}
#define CPA_COMMIT() asm volatile("cp.async.commit_group;" ::: "memory")
#define CPA_WAIT1()  asm volatile("cp.async.wait_group 1;" ::: "memory")
#define CPA_WAIT0()  asm volatile("cp.async.wait_group 0;" ::: "memory")

__device__ __forceinline__ void split4(float4 v, uint2& h, uint2& l) {
    __nv_bfloat16 hx = __float2bfloat16(v.x), hy = __float2bfloat16(v.y);
    __nv_bfloat16 hz = __float2bfloat16(v.z), hw = __float2bfloat16(v.w);
    __nv_bfloat16 lx = __float2bfloat16(v.x - __bfloat162float(hx));
    __nv_bfloat16 ly = __float2bfloat16(v.y - __bfloat162float(hy));
    __nv_bfloat16 lz = __float2bfloat16(v.z - __bfloat162float(hz));
    __nv_bfloat16 lw = __float2bfloat16(v.w - __bfloat162float(hw));
    __nv_bfloat162 h0 = __halves2bfloat162(hx, hy), h1 = __halves2bfloat162(hz, hw);
    __nv_bfloat162 l0 = __halves2bfloat162(lx, ly), l1 = __halves2bfloat162(lz, lw);
    h.x = *(uint32_t*)&h0; h.y = *(uint32_t*)&h1;
    l.x = *(uint32_t*)&l0; l.y = *(uint32_t*)&l1;
}

__device__ __forceinline__ uint32_t pack2(float a, float b) {
    uint32_t r;
    asm("cvt.rn.bf16x2.f32 %0, %1, %2;" : "=r"(r) : "f"(b), "f"(a));
    return r;
}

// ======================= presplit: fp32 -> hi/lo bf16 =======================
__global__ __launch_bounds__(256)
void presplit(const float* __restrict__ in, __nv_bfloat16* __restrict__ hi,
              __nv_bfloat16* __restrict__ lo) {
    const int i = blockIdx.x * blockDim.x + threadIdx.x;
    float4 v = ((const float4*)in)[i];
    uint2 h, l;
    split4(v, h, l);
    ((uint2*)hi)[i] = h;
    ((uint2*)lo)[i] = l;
}

// ======================= pipelined hi/lo mma GEMM (validated R11) ==========
#define ROWS   80
#define ST_AH  0
#define ST_AL  10240
#define ST_BH  20480
#define ST_BL  40960
#define STAGE  61440
#define GEMM_SMEM (2 * STAGE)

__global__ __launch_bounds__(256, 1)
void gemm_pipe(const __nv_bfloat16* __restrict__ Ah, const __nv_bfloat16* __restrict__ Al,
               const __nv_bfloat16* __restrict__ Wh, const __nv_bfloat16* __restrict__ Wl,
               float* __restrict__ C) {
    extern __shared__ __align__(16) char smem[];
    constexpr int K = DMODEL, N = DMODEL, NC = K / 32;

    const int tid = threadIdx.x;
    const int lane = tid & 31, wid = tid >> 5;
    const int warp_m = wid >> 2;
    const int warp_n = wid & 3;
    const int bm = blockIdx.y * 128;
    const int bn = blockIdx.x * 256;
    const int third = blockIdx.y >> 5;
    const __nv_bfloat16* WhS = Wh + (size_t)third * DD;
    const __nv_bfloat16* WlS = Wl + (size_t)third * DD;
    const uint32_t sb = smem_u32(smem);

    const int lrow = tid >> 2;
    const int lc = (tid & 3) * 16;

    auto issue = [&](int buf, int k0) {
        const uint32_t st = sb + buf * STAGE;
#pragma unroll
        for (int j = 0; j < 2; j++) {
            const int row = lrow + j * 64;
            const size_t g = (size_t)(bm + row) * K + k0 + (lc >> 1);
            cpa16(st + ST_AH + row * ROWS + lc, Ah + g);
            cpa16(st + ST_AL + row * ROWS + lc, Al + g);
        }
#pragma unroll
        for (int j = 0; j < 4; j++) {
            const int row = lrow + j * 64;
            const size_t g = (size_t)(bn + row) * K + k0 + (lc >> 1);
            cpa16(st + ST_BH + row * ROWS + lc, WhS + g);
            cpa16(st + ST_BL + row * ROWS + lc, WlS + g);
        }
    };

    float acc[4][8][4];
#pragma unroll
    for (int mt = 0; mt < 4; mt++)
#pragma unroll
        for (int nt = 0; nt < 8; nt++)
#pragma unroll
            for (int r = 0; r < 4; r++) acc[mt][nt][r] = 0.f;

    const int a_row = warp_m * 64 + (lane & 15);
    const uint32_t a_half = (uint32_t)(lane >> 4) * 16;
    const int b_row = warp_n * 64 + (lane & 7) + ((lane >> 4) & 1) * 8;
    const uint32_t b_half = (uint32_t)((lane >> 3) & 1) * 16;

    issue(0, 0);
    CPA_COMMIT();

    for (int c = 0; c < NC; c++) {
        if (c + 1 < NC) {
            issue((c + 1) & 1, (c + 1) * 32);
            CPA_COMMIT();
            CPA_WAIT1();
        } else {
            CPA_WAIT0();
        }
        __syncthreads();

        const uint32_t st = sb + (c & 1) * STAGE;
#pragma unroll
        for (int ks = 0; ks < 2; ks++) {
            const uint32_t koff = (uint32_t)ks * 32;
            uint32_t ah[4][4], al[4][4];
#pragma unroll
            for (int mt = 0; mt < 4; mt++) {
                const uint32_t ra = (uint32_t)(a_row + mt * 16) * ROWS + koff + a_half;
                LDMATRIX_X4(ah[mt][0], ah[mt][1], ah[mt][2], ah[mt][3], st + ST_AH + ra);
                LDMATRIX_X4(al[mt][0], al[mt][1], al[mt][2], al[mt][3], st + ST_AL + ra);
            }
#pragma unroll
            for (int nt2 = 0; nt2 < 4; nt2++) {
                uint32_t bh[4], bl[4];
                const uint32_t rb = (uint32_t)(b_row + nt2 * 16) * ROWS + koff + b_half;
                LDMATRIX_X4(bh[0], bh[1], bh[2], bh[3], st + ST_BH + rb);
                LDMATRIX_X4(bl[0], bl[1], bl[2], bl[3], st + ST_BL + rb);
#pragma unroll
                for (int j = 0; j < 2; j++) {
                    const int nt = nt2 * 2 + j;
#pragma unroll
                    for (int mt = 0; mt < 4; mt++) {
                        MMA16816(acc[mt][nt], ah[mt], bh[j * 2], bh[j * 2 + 1]);
                        MMA16816(acc[mt][nt], al[mt], bh[j * 2], bh[j * 2 + 1]);
                        MMA16816(acc[mt][nt], ah[mt], bl[j * 2], bl[j * 2 + 1]);
                    }
                }
            }
        }
        __syncthreads();
    }

    const int erow = bm + warp_m * 64 + (lane >> 2);
    const int ecol = bn + warp_n * 64 + (lane & 3) * 2;
#pragma unroll
    for (int mt = 0; mt < 4; mt++)
#pragma unroll
        for (int nt = 0; nt < 8; nt++) {
            float* c0 = &C[(size_t)(erow + mt * 16) * N + ecol + nt * 8];
            float* c1 = &C[(size_t)(erow + mt * 16 + 8) * N + ecol + nt * 8];
            *(float2*)c0 = make_float2(acc[mt][nt][0], acc[mt][nt][1]);
            *(float2*)c1 = make_float2(acc[mt][nt][2], acc[mt][nt][3]);
        }
}

// ======================= mask bit-pack (validated R7) =======================
__global__ __launch_bounds__(256)
void mask_pack(const uint32_t* __restrict__ m, uint32_t* __restrict__ out) {
    const int gwarp = (blockIdx.x * blockDim.x + threadIdx.x) >> 5;
    const int lane = threadIdx.x & 31;
    const uint32_t* base = m + (size_t)gwarp * 1024;
    uint32_t my = 0;
#pragma unroll 4
    for (int g = 0; g < 32; g++) {
        uint32_t v = base[g * 32 + lane];
        uint32_t bal = __ballot_sync(0xffffffffu, v != 0);
        if (lane == g) my = bal;
    }
    out[(size_t)gwarp * 32 + lane] = my;
}

// ======================= tensor-core flash attention (pipelined) ===========
// K/V read as pre-split bf16 hi/lo via cp.async double-buffer.
// V stays row-major [key][d]; P.V B-fragments via ldmatrix.x4.trans.
#define ROWB   144
#define SK_H   0
#define SK_L   9216
#define SV_H   18432
#define SV_L   27648
#define STG_F  36864
#define FLASH_SMEM (2 * STG_F)   // 73728
#define AT_QH  0
#define AT_QL  18432

__global__ __launch_bounds__(256)
void flash_mma(const float* __restrict__ Qp,
               const __nv_bfloat16* __restrict__ KHg, const __nv_bfloat16* __restrict__ KLg,
               const __nv_bfloat16* __restrict__ VHg, const __nv_bfloat16* __restrict__ VLg,
               const uint32_t* __restrict__ mpk, float* __restrict__ Ctx) {
    extern __shared__ __align__(16) char smem[];
    const int b = blockIdx.z, h = blockIdx.y;
    const int tid = threadIdx.x, lane = tid & 31, wid = tid >> 5;
    const int bm = blockIdx.x * 128;
    const uint32_t sb = smem_u32(smem);

    // ---- stage Q (scaled), split hi/lo, into stage-0 area (consumed before pipeline) ----
    {
        const int row = tid >> 1;
        const int half = (tid & 1) * 32;
        const float4* qsrc = (const float4*)&Qp[((size_t)b * SEQ + bm + row) * DMODEL + h * DK + half];
        char* pH = smem + AT_QH + row * ROWB + half * 2;
        char* pL = smem + AT_QL + row * ROWB + half * 2;
#pragma unroll
        for (int i = 0; i < 8; i++) {
            float4 v = qsrc[i];
            v.x *= 0.125f; v.y *= 0.125f; v.z *= 0.125f; v.w *= 0.125f;
            uint2 hh, ll;
            split4(v, hh, ll);
            *(uint2*)(pH + i * 8) = hh;
            *(uint2*)(pL + i * 8) = ll;
        }
    }
    __syncthreads();

    uint32_t qh[4][4], ql[4][4];
    {
        const int a_row = wid * 16 + (lane & 15);
        const uint32_t a_off = (uint32_t)(lane >> 4) * 16;
#pragma unroll
        for (int ks = 0; ks < 4; ks++) {
            const uint32_t ra = (uint32_t)a_row * ROWB + (uint32_t)ks * 32 + a_off;
            LDMATRIX_X4(qh[ks][0], qh[ks][1], qh[ks][2], qh[ks][3], sb + AT_QH + ra);
            LDMATRIX_X4(ql[ks][0], ql[ks][1], ql[ks][2], ql[ks][3], sb + AT_QL + ra);
        }
    }
    __syncthreads();   // Q fully consumed before cp.async overwrites stage 0

    // cp.async staging of one 64-key chunk (KH/KL/VH/VL, 64x64 bf16 each)
    const int srow = tid >> 2;           // 0..63
    const int scb = (tid & 3) * 32;      // byte offset 0,32,64,96
    auto issue = [&](int buf, int n0) {
        const uint32_t st = sb + buf * STG_F;
        const size_t g = ((size_t)b * SEQ + n0 + srow) * DMODEL + h * DK + (scb >> 1);
        const uint32_t ro = (uint32_t)srow * ROWB + scb;
        cpa16(st + SK_H + ro,      KHg + g);
        cpa16(st + SK_H + ro + 16, KHg + g + 8);
        cpa16(st + SK_L + ro,      KLg + g);
        cpa16(st + SK_L + ro + 16, KLg + g + 8);
        cpa16(st + SV_H + ro,      VHg + g);
        cpa16(st + SV_H + ro + 16, VHg + g + 8);
        cpa16(st + SV_L + ro,      VLg + g);
        cpa16(st + SV_L + ro + 16, VLg + g + 8);
    };

    float o[8][4];
#pragma unroll
    for (int nt = 0; nt < 8; nt++)
#pragma unroll
        for (int r = 0; r < 4; r++) o[nt][r] = 0.f;
    float m0 = -3.0e38f, m1 = -3.0e38f, l0 = 0.f, l1 = 0.f;

    const int r0 = bm + wid * 16 + (lane >> 2);
    const uint32_t* mrow0 = &mpk[((size_t)b * SEQ + r0) * (SEQ / 32)];
    const uint32_t* mrow1 = mrow0 + 8 * (SEQ / 32);

    const int b_row = (lane & 7) + ((lane >> 4) & 1) * 8;
    const uint32_t b_off = (uint32_t)((lane >> 3) & 1) * 16;
    const int v_row = (lane & 7) + ((lane >> 3) & 1) * 8;      // trans pattern
    const uint32_t v_off = (uint32_t)((lane >> 4) & 1) * 16;
    const int colbase = (lane & 3) * 2;

    issue(0, 0);
    CPA_COMMIT();

    for (int c = 0; c < SEQ / 64; c++) {
        if (c + 1 < SEQ / 64) {
            issue((c + 1) & 1, (c + 1) * 64);
            CPA_COMMIT();
            CPA_WAIT1();
        } else {
            CPA_WAIT0();
        }
        __syncthreads();
        const uint32_t st = sb + (c & 1) * STG_F;

        // ---- S = Q K^T (3 passes) ----
        float s[8][4];
#pragma unroll
        for (int nt = 0; nt < 8; nt++)
#pragma unroll
            for (int r = 0; r < 4; r++) s[nt][r] = 0.f;

#pragma unroll
        for (int ks = 0; ks < 4; ks++) {
#pragma unroll
            for (int nt2 = 0; nt2 < 4; nt2++) {
                uint32_t kh[4], kl[4];
                const uint32_t rb = (uint32_t)(b_row + nt2 * 16) * ROWB + (uint32_t)ks * 32 + b_off;
                LDMATRIX_X4(kh[0], kh[1], kh[2], kh[3], st + SK_H + rb);
                LDMATRIX_X4(kl[0], kl[1], kl[2], kl[3], st + SK_L + rb);
#pragma unroll
                for (int j = 0; j < 2; j++) {
                    const int nt = nt2 * 2 + j;
                    MMA16816(s[nt], qh[ks], kh[j * 2], kh[j * 2 + 1]);
                    MMA16816(s[nt], ql[ks], kh[j * 2], kh[j * 2 + 1]);
                    MMA16816(s[nt], qh[ks], kl[j * 2], kl[j * 2 + 1]);
                }
            }
        }

        // ---- mask ----
        {
            const uint64_t mk0 = (uint64_t)mrow0[c * 2] | ((uint64_t)mrow0[c * 2 + 1] << 32);
            const uint64_t mk1 = (uint64_t)mrow1[c * 2] | ((uint64_t)mrow1[c * 2 + 1] << 32);
#pragma unroll
            for (int nt = 0; nt < 8; nt++) {
                const int col = nt * 8 + colbase;
                s[nt][0] += ((mk0 >> col) & 1) ? -1e9f : 0.f;
                s[nt][1] += ((mk0 >> (col + 1)) & 1) ? -1e9f : 0.f;
                s[nt][2] += ((mk1 >> col) & 1) ? -1e9f : 0.f;
                s[nt][3] += ((mk1 >> (col + 1)) & 1) ? -1e9f : 0.f;
            }
        }

        // ---- online softmax ----
        float cm0 = -3.0e38f, cm1 = -3.0e38f;
#pragma unroll
        for (int nt = 0; nt < 8; nt++) {
            cm0 = fmaxf(cm0, fmaxf(s[nt][0], s[nt][1]));
            cm1 = fmaxf(cm1, fmaxf(s[nt][2], s[nt][3]));
        }
        cm0 = fmaxf(cm0, __shfl_xor_sync(0xffffffffu, cm0, 1));
        cm0 = fmaxf(cm0, __shfl_xor_sync(0xffffffffu, cm0, 2));
        cm1 = fmaxf(cm1, __shfl_xor_sync(0xffffffffu, cm1, 1));
        cm1 = fmaxf(cm1, __shfl_xor_sync(0xffffffffu, cm1, 2));

        const float mn0 = fmaxf(m0, cm0), mn1 = fmaxf(m1, cm1);
        const float sc0 = __expf(m0 - mn0), sc1 = __expf(m1 - mn1);
        l0 *= sc0; l1 *= sc1;
#pragma unroll
        for (int nt = 0; nt < 8; nt++) {
            o[nt][0] *= sc0; o[nt][1] *= sc0;
            o[nt][2] *= sc1; o[nt][3] *= sc1;
        }
        m0 = mn0; m1 = mn1;

        uint32_t aPh[4][4], aPl[4][4];
#pragma unroll
        for (int nt = 0; nt < 8; nt++) {
            float p0 = __expf(s[nt][0] - mn0);
            float p1 = __expf(s[nt][1] - mn0);
            float p2 = __expf(s[nt][2] - mn1);
            float p3 = __expf(s[nt][3] - mn1);
            l0 += p0 + p1; l1 += p2 + p3;
            const int t = nt >> 1, jj = (nt & 1) * 2;
            uint32_t hp01 = pack2(p0, p1), hp23 = pack2(p2, p3);
            __nv_bfloat162 hb01 = *(__nv_bfloat162*)&hp01;
            __nv_bfloat162 hb23 = *(__nv_bfloat162*)&hp23;
            uint32_t lp01 = pack2(p0 - __bfloat162float(hb01.x), p1 - __bfloat162float(hb01.y));
            uint32_t lp23 = pack2(p2 - __bfloat162float(hb23.x), p3 - __bfloat162float(hb23.y));
            aPh[t][jj] = hp01; aPh[t][jj + 1] = hp23;
            aPl[t][jj] = lp01; aPl[t][jj + 1] = lp23;
        }

        // ---- O += P V (3 passes, trans B fragments from row-major V) ----
#pragma unroll
        for (int t = 0; t < 4; t++) {
#pragma unroll
            for (int nt2 = 0; nt2 < 4; nt2++) {
                uint32_t vh[4], vl[4];
                const uint32_t rb = (uint32_t)(t * 16 + v_row) * ROWB + (uint32_t)nt2 * 32 + v_off;
                LDMATRIX_X4_T(vh[0], vh[1], vh[2], vh[3], st + SV_H + rb);
                LDMATRIX_X4_T(vl[0], vl[1], vl[2], vl[3], st + SV_L + rb);
#pragma unroll
                for (int j = 0; j < 2; j++) {
                    const int nt = nt2 * 2 + j;
                    MMA16816(o[nt], aPh[t], vh[j * 2], vh[j * 2 + 1]);
                    MMA16816(o[nt], aPl[t], vh[j * 2], vh[j * 2 + 1]);
                    MMA16816(o[nt], aPh[t], vl[j * 2], vl[j * 2 + 1]);
                }
            }
        }
        __syncthreads();
    }

    // ---- epilogue ----
    l0 += __shfl_xor_sync(0xffffffffu, l0, 1);
    l0 += __shfl_xor_sync(0xffffffffu, l0, 2);
    l1 += __shfl_xor_sync(0xffffffffu, l1, 1);
    l1 += __shfl_xor_sync(0xffffffffu, l1, 2);
    const float inv0 = 1.f / l0, inv1 = 1.f / l1;

    const int ecol = h * DK + (lane & 3) * 2;
    float* out0 = &Ctx[((size_t)b * SEQ + r0) * DMODEL + ecol];
    float* out1 = &Ctx[((size_t)b * SEQ + r0 + 8) * DMODEL + ecol];
#pragma unroll
    for (int nt = 0; nt < 8; nt++) {
        *(float2*)(out0 + nt * 8) = make_float2(o[nt][0] * inv0, o[nt][1] * inv0);
        *(float2*)(out1 + nt * 8) = make_float2(o[nt][2] * inv1, o[nt][3] * inv1);
    }
}

// ---------------------------------------------------------------
extern "C" void kernel_launch(void* const* d_in, const int* in_sizes, int n_in,
                              void* d_out, int out_size) {
    const float*    q    = (const float*)d_in[0];
    const float*    k    = (const float*)d_in[1];
    const float*    v    = (const float*)d_in[2];
    const uint32_t* mask = (const uint32_t*)d_in[3];
    const float*    Wq   = (const float*)d_in[4];
    const float*    Wk   = (const float*)d_in[5];
    const float*    Wv   = (const float*)d_in[6];
    const float*    Wo   = (const float*)d_in[7];
    float* out = (float*)d_out;

    float *QKVp, *Ctx;
    __nv_bfloat16 *AH, *AL, *WH, *WL;
    uint32_t* mpk;
    cudaGetSymbolAddress((void**)&QKVp, g_QKVp);
    cudaGetSymbolAddress((void**)&Ctx,  g_Ctx);
    cudaGetSymbolAddress((void**)&AH,   g_AH);
    cudaGetSymbolAddress((void**)&AL,   g_AL);
    cudaGetSymbolAddress((void**)&WH,   g_WH);
    cudaGetSymbolAddress((void**)&WL,   g_WL);
    cudaGetSymbolAddress((void**)&mpk,  g_mpk);

    cudaFuncSetAttribute(gemm_pipe, cudaFuncAttributeMaxDynamicSharedMemorySize, GEMM_SMEM);
    cudaFuncSetAttribute(flash_mma, cudaFuncAttributeMaxDynamicSharedMemorySize, FLASH_SMEM);

    const size_t AD = (size_t)GM * DMODEL;
    const int gA = (int)(AD / 4 / 256);
    const int gW = DD / 4 / 256;

    presplit<<<gA, 256>>>(q, AH, AL);
    presplit<<<gA, 256>>>(k, AH + AD, AL + AD);
    presplit<<<gA, 256>>>(v, AH + 2 * AD, AL + 2 * AD);
    presplit<<<gW, 256>>>(Wq, WH, WL);
    presplit<<<gW, 256>>>(Wk, WH + DD, WL + DD);
    presplit<<<gW, 256>>>(Wv, WH + 2 * DD, WL + 2 * DD);
    presplit<<<gW, 256>>>(Wo, WH + 3 * DD, WL + 3 * DD);
    mask_pack<<<1024, 256>>>(mask, mpk);

    dim3 gqkv(DMODEL / 256, 3 * GM / 128);
    gemm_pipe<<<gqkv, 256, GEMM_SMEM>>>(AH, AL, WH, WL, QKVp);

    // re-split projected K and V to bf16 hi/lo (AH/AL reusable now)
    presplit<<<gA, 256>>>(QKVp + AD, AH, AL);                 // K -> KH,KL
    presplit<<<gA, 256>>>(QKVp + 2 * AD, AH + AD, AL + AD);   // V -> VH,VL

    dim3 ga(SEQ / 128, NHEADS, BATCH);
    flash_mma<<<ga, 256, FLASH_SMEM>>>(QKVp, AH, AL, AH + AD, AL + AD, mpk, Ctx);

    presplit<<<gA, 256>>>(Ctx, AH + 2 * AD, AL + 2 * AD);
    dim3 go(DMODEL / 256, GM / 128);
    gemm_pipe<<<go, 256, GEMM_SMEM>>>(AH + 2 * AD, AL + 2 * AD, WH + 3 * DD, WL + 3 * DD, out);
}

// round 15
// speedup vs baseline: 3.1907x; 1.0189x over previous
#include <cuda_runtime.h>
#include <cuda_bf16.h>
#include <cstdint>

#define BATCH  2
#define SEQ    2048
#define DMODEL 1024
#define NHEADS 16
#define DK     64
#define GM     (BATCH * SEQ)
#define DD     (DMODEL * DMODEL)

// ---------------- scratch (no cudaMalloc allowed) ----------------
// AH/AL: input splits for QKV gemm, then reused for Ctx hi/lo (first AD).
// BH/BL: projected Q/K/V hi/lo.
__device__ __nv_bfloat16 g_AH[(size_t)3 * GM * DMODEL];
__device__ __nv_bfloat16 g_AL[(size_t)3 * GM * DMODEL];
__device__ __nv_bfloat16 g_BH[(size_t)3 * GM * DMODEL];
__device__ __nv_bfloat16 g_BL[(size_t)3 * GM * DMODEL];
__device__ __nv_bfloat16 g_WH[(size_t)4 * DD];
__device__ __nv_bfloat16 g_WL[(size_t)4 * DD];
__device__ uint32_t g_mpk[(size_t)BATCH * SEQ * (SEQ / 32)];

// ======================= common helpers =======================
#define LDMATRIX_X4(r0, r1, r2, r3, addr)                                   \
    asm volatile("ldmatrix.sync.aligned.m8n8.x4.shared.b16 {%0,%1,%2,%3}, [%4];" \
                 : "=r"(r0), "=r"(r1), "=r"(r2), "=r"(r3) : "r"(addr))

#define LDMATRIX_X4_T(r0, r1, r2, r3, addr)                                 \
    asm volatile("ldmatrix.sync.aligned.m8n8.x4.trans.shared.b16 {%0,%1,%2,%3}, [%4];" \
                 : "=r"(r0), "=r"(r1), "=r"(r2), "=r"(r3) : "r"(addr))

#define MMA16816(d, a, b0, b1)                                              \
    asm volatile("mma.sync.aligned.m16n8k16.row.col.f32.bf16.bf16.f32 "     \
                 "{%0,%1,%2,%3}, {%4,%5,%6,%7}, {%8,%9}, {%0,%1,%2,%3};"    \
                 : "+f"((d)[0]), "+f"((d)[1]), "+f"((d)[2]), "+f"((d)[3])   \
                 : "r"((a)[0]), "r"((a)[1]), "r"((a)[2]), "r"((a)[3]),      \
                   "r"(b0), "r"(b1))

__device__ __forceinline__ uint32_t smem_u32(const void* p) {
    uint32_t a;
    asm("{ .reg .u64 t; cvta.to.shared.u64 t, %1; cvt.u32.u64 %0, t; }" : "=r"(a) : "l"(p));
    return a;
}

__device__ __forceinline__ void cpa16(uint32_t saddr, const void* g) {
    asm volatile("cp.async.cg.shared.global [%0], [%1], 16;" :: "r"(saddr), "l"(g));
}
#define CPA_COMMIT() asm volatile("cp.async.commit_group;" ::: "memory")
#define CPA_WAIT1()  asm volatile("cp.async.wait_group 1;" ::: "memory")
#define CPA_WAIT0()  asm volatile("cp.async.wait_group 0;" ::: "memory")

__device__ __forceinline__ void split4(float4 v, uint2& h, uint2& l) {
    __nv_bfloat16 hx = __float2bfloat16(v.x), hy = __float2bfloat16(v.y);
    __nv_bfloat16 hz = __float2bfloat16(v.z), hw = __float2bfloat16(v.w);
    __nv_bfloat16 lx = __float2bfloat16(v.x - __bfloat162float(hx));
    __nv_bfloat16 ly = __float2bfloat16(v.y - __bfloat162float(hy));
    __nv_bfloat16 lz = __float2bfloat16(v.z - __bfloat162float(hz));
    __nv_bfloat16 lw = __float2bfloat16(v.w - __bfloat162float(hw));
    __nv_bfloat162 h0 = __halves2bfloat162(hx, hy), h1 = __halves2bfloat162(hz, hw);
    __nv_bfloat162 l0 = __halves2bfloat162(lx, ly), l1 = __halves2bfloat162(lz, lw);
    h.x = *(uint32_t*)&h0; h.y = *(uint32_t*)&h1;
    l.x = *(uint32_t*)&l0; l.y = *(uint32_t*)&l1;
}

__device__ __forceinline__ uint32_t pack2(float a, float b) {
    uint32_t r;
    asm("cvt.rn.bf16x2.f32 %0, %1, %2;" : "=r"(r) : "f"(b), "f"(a));
    return r;
}

// hi/lo split of a float pair -> two u32 (bf16x2)
__device__ __forceinline__ void split_pair(float x, float y, uint32_t& hp, uint32_t& lp) {
    hp = pack2(x, y);
    __nv_bfloat162 hb = *(__nv_bfloat162*)&hp;
    lp = pack2(x - __bfloat162float(hb.x), y - __bfloat162float(hb.y));
}

// ======================= presplit kernels =======================
// activations: grid.y selects q/k/v
__global__ __launch_bounds__(256)
void presplit_a(const float* __restrict__ a0, const float* __restrict__ a1,
                const float* __restrict__ a2,
                __nv_bfloat16* __restrict__ hi, __nv_bfloat16* __restrict__ lo) {
    const int t = blockIdx.y;
    const float* src = (t == 0) ? a0 : (t == 1) ? a1 : a2;
    const size_t base = (size_t)t * (GM * DMODEL / 4);
    const size_t i = base + blockIdx.x * blockDim.x + threadIdx.x;
    float4 v = ((const float4*)src)[i - base];
    uint2 h, l;
    split4(v, h, l);
    ((uint2*)hi)[i] = h;
    ((uint2*)lo)[i] = l;
}

// weights: grid.y selects Wq/Wk/Wv/Wo; Wq pre-scaled by 0.125 (exact)
__global__ __launch_bounds__(256)
void presplit_w(const float* __restrict__ w0, const float* __restrict__ w1,
                const float* __restrict__ w2, const float* __restrict__ w3,
                __nv_bfloat16* __restrict__ hi, __nv_bfloat16* __restrict__ lo) {
    const int t = blockIdx.y;
    const float* src = (t == 0) ? w0 : (t == 1) ? w1 : (t == 2) ? w2 : w3;
    const float sc = (t == 0) ? 0.125f : 1.0f;
    const size_t base = (size_t)t * (DD / 4);
    const size_t i = base + blockIdx.x * blockDim.x + threadIdx.x;
    float4 v = ((const float4*)src)[i - base];
    v.x *= sc; v.y *= sc; v.z *= sc; v.w *= sc;
    uint2 h, l;
    split4(v, h, l);
    ((uint2*)hi)[i] = h;
    ((uint2*)lo)[i] = l;
}

// ======================= pipelined hi/lo mma GEMM =======================
#define ROWS   80
#define ST_AH  0
#define ST_AL  10240
#define ST_BH  20480
#define ST_BL  40960
#define STAGE  61440
#define GEMM_SMEM (2 * STAGE)

__global__ __launch_bounds__(256, 1)
void gemm_pipe(const __nv_bfloat16* __restrict__ Ah, const __nv_bfloat16* __restrict__ Al,
               const __nv_bfloat16* __restrict__ Wh, const __nv_bfloat16* __restrict__ Wl,
               float* __restrict__ C, __nv_bfloat16* __restrict__ CH,
               __nv_bfloat16* __restrict__ CL, int wantf32) {
    extern __shared__ __align__(16) char smem[];
    constexpr int K = DMODEL, N = DMODEL, NC = K / 32;

    const int tid = threadIdx.x;
    const int lane = tid & 31, wid = tid >> 5;
    const int warp_m = wid >> 2;
    const int warp_n = wid & 3;
    const int bm = blockIdx.y * 128;
    const int bn = blockIdx.x * 256;
    const int third = blockIdx.y >> 5;
    const __nv_bfloat16* WhS = Wh + (size_t)third * DD;
    const __nv_bfloat16* WlS = Wl + (size_t)third * DD;
    const uint32_t sb = smem_u32(smem);

    const int lrow = tid >> 2;
    const int lc = (tid & 3) * 16;

    auto issue = [&](int buf, int k0) {
        const uint32_t st = sb + buf * STAGE;
#pragma unroll
        for (int j = 0; j < 2; j++) {
            const int row = lrow + j * 64;
            const size_t g = (size_t)(bm + row) * K + k0 + (lc >> 1);
            cpa16(st + ST_AH + row * ROWS + lc, Ah + g);
            cpa16(st + ST_AL + row * ROWS + lc, Al + g);
        }
#pragma unroll
        for (int j = 0; j < 4; j++) {
            const int row = lrow + j * 64;
            const size_t g = (size_t)(bn + row) * K + k0 + (lc >> 1);
            cpa16(st + ST_BH + row * ROWS + lc, WhS + g);
            cpa16(st + ST_BL + row * ROWS + lc, WlS + g);
        }
    };

    float acc[4][8][4];
#pragma unroll
    for (int mt = 0; mt < 4; mt++)
#pragma unroll
        for (int nt = 0; nt < 8; nt++)
#pragma unroll
            for (int r = 0; r < 4; r++) acc[mt][nt][r] = 0.f;

    const int a_row = warp_m * 64 + (lane & 15);
    const uint32_t a_half = (uint32_t)(lane >> 4) * 16;
    const int b_row = warp_n * 64 + (lane & 7) + ((lane >> 4) & 1) * 8;
    const uint32_t b_half = (uint32_t)((lane >> 3) & 1) * 16;

    issue(0, 0);
    CPA_COMMIT();

    for (int c = 0; c < NC; c++) {
        if (c + 1 < NC) {
            issue((c + 1) & 1, (c + 1) * 32);
            CPA_COMMIT();
            CPA_WAIT1();
        } else {
            CPA_WAIT0();
        }
        __syncthreads();

        const uint32_t st = sb + (c & 1) * STAGE;
#pragma unroll
        for (int ks = 0; ks < 2; ks++) {
            const uint32_t koff = (uint32_t)ks * 32;
            uint32_t ah[4][4], al[4][4];
#pragma unroll
            for (int mt = 0; mt < 4; mt++) {
                const uint32_t ra = (uint32_t)(a_row + mt * 16) * ROWS + koff + a_half;
                LDMATRIX_X4(ah[mt][0], ah[mt][1], ah[mt][2], ah[mt][3], st + ST_AH + ra);
                LDMATRIX_X4(al[mt][0], al[mt][1], al[mt][2], al[mt][3], st + ST_AL + ra);
            }
#pragma unroll
            for (int nt2 = 0; nt2 < 4; nt2++) {
                uint32_t bh[4], bl[4];
                const uint32_t rb = (uint32_t)(b_row + nt2 * 16) * ROWS + koff + b_half;
                LDMATRIX_X4(bh[0], bh[1], bh[2], bh[3], st + ST_BH + rb);
                LDMATRIX_X4(bl[0], bl[1], bl[2], bl[3], st + ST_BL + rb);
#pragma unroll
                for (int j = 0; j < 2; j++) {
                    const int nt = nt2 * 2 + j;
#pragma unroll
                    for (int mt = 0; mt < 4; mt++) {
                        MMA16816(acc[mt][nt], ah[mt], bh[j * 2], bh[j * 2 + 1]);
                        MMA16816(acc[mt][nt], al[mt], bh[j * 2], bh[j * 2 + 1]);
                        MMA16816(acc[mt][nt], ah[mt], bl[j * 2], bl[j * 2 + 1]);
                    }
                }
            }
        }
        __syncthreads();
    }

    const int erow = bm + warp_m * 64 + (lane >> 2);
    const int ecol = bn + warp_n * 64 + (lane & 3) * 2;
    if (wantf32) {
#pragma unroll
        for (int mt = 0; mt < 4; mt++)
#pragma unroll
            for (int nt = 0; nt < 8; nt++) {
                float* c0 = &C[(size_t)(erow + mt * 16) * N + ecol + nt * 8];
                float* c1 = &C[(size_t)(erow + mt * 16 + 8) * N + ecol + nt * 8];
                *(float2*)c0 = make_float2(acc[mt][nt][0], acc[mt][nt][1]);
                *(float2*)c1 = make_float2(acc[mt][nt][2], acc[mt][nt][3]);
            }
    } else {
#pragma unroll
        for (int mt = 0; mt < 4; mt++)
#pragma unroll
            for (int nt = 0; nt < 8; nt++) {
                const size_t i0 = (size_t)(erow + mt * 16) * N + ecol + nt * 8;
                const size_t i1 = (size_t)(erow + mt * 16 + 8) * N + ecol + nt * 8;
                uint32_t hp, lp;
                split_pair(acc[mt][nt][0], acc[mt][nt][1], hp, lp);
                *(uint32_t*)&CH[i0] = hp; *(uint32_t*)&CL[i0] = lp;
                split_pair(acc[mt][nt][2], acc[mt][nt][3], hp, lp);
                *(uint32_t*)&CH[i1] = hp; *(uint32_t*)&CL[i1] = lp;
            }
    }
}

// ======================= mask bit-pack (validated R7) =======================
__global__ __launch_bounds__(256)
void mask_pack(const uint32_t* __restrict__ m, uint32_t* __restrict__ out) {
    const int gwarp = (blockIdx.x * blockDim.x + threadIdx.x) >> 5;
    const int lane = threadIdx.x & 31;
    const uint32_t* base = m + (size_t)gwarp * 1024;
    uint32_t my = 0;
#pragma unroll 4
    for (int g = 0; g < 32; g++) {
        uint32_t v = base[g * 32 + lane];
        uint32_t bal = __ballot_sync(0xffffffffu, v != 0);
        if (lane == g) my = bal;
    }
    out[(size_t)gwarp * 32 + lane] = my;
}

// ======================= tensor-core flash attention (pipelined) ===========
// Q/K/V all pre-split bf16 hi/lo in global (Q pre-scaled via Wq).
#define ROWB   144
#define SK_H   0
#define SK_L   9216
#define SV_H   18432
#define SV_L   27648
#define STG_F  36864
#define FLASH_SMEM (2 * STG_F)
#define AT_QH  0
#define AT_QL  18432

__global__ __launch_bounds__(256)
void flash_mma(const __nv_bfloat16* __restrict__ QHg, const __nv_bfloat16* __restrict__ QLg,
               const __nv_bfloat16* __restrict__ KHg, const __nv_bfloat16* __restrict__ KLg,
               const __nv_bfloat16* __restrict__ VHg, const __nv_bfloat16* __restrict__ VLg,
               const uint32_t* __restrict__ mpk,
               __nv_bfloat16* __restrict__ CtxH, __nv_bfloat16* __restrict__ CtxL) {
    extern __shared__ __align__(16) char smem[];
    const int b = blockIdx.z, h = blockIdx.y;
    const int tid = threadIdx.x, lane = tid & 31, wid = tid >> 5;
    const int bm = blockIdx.x * 128;
    const uint32_t sb = smem_u32(smem);

    // ---- stage Q hi/lo via cp.async into stage-0 area ----
    {
        const int qrow = tid >> 1;                 // 0..127
        const uint32_t qco = (uint32_t)(tid & 1) * 64;  // byte offset in 128B row
        const size_t gq = ((size_t)b * SEQ + bm + qrow) * DMODEL + h * DK + (qco >> 1);
        const uint32_t ro = (uint32_t)qrow * ROWB + qco;
#pragma unroll
        for (int i = 0; i < 4; i++) {
            cpa16(sb + AT_QH + ro + i * 16, QHg + gq + i * 8);
            cpa16(sb + AT_QL + ro + i * 16, QLg + gq + i * 8);
        }
    }
    CPA_COMMIT();
    CPA_WAIT0();
    __syncthreads();

    uint32_t qh[4][4], ql[4][4];
    {
        const int a_row = wid * 16 + (lane & 15);
        const uint32_t a_off = (uint32_t)(lane >> 4) * 16;
#pragma unroll
        for (int ks = 0; ks < 4; ks++) {
            const uint32_t ra = (uint32_t)a_row * ROWB + (uint32_t)ks * 32 + a_off;
            LDMATRIX_X4(qh[ks][0], qh[ks][1], qh[ks][2], qh[ks][3], sb + AT_QH + ra);
            LDMATRIX_X4(ql[ks][0], ql[ks][1], ql[ks][2], ql[ks][3], sb + AT_QL + ra);
        }
    }
    __syncthreads();   // Q consumed before pipeline reuses stage 0

    const int srow = tid >> 2;
    const int scb = (tid & 3) * 32;
    auto issue = [&](int buf, int n0) {
        const uint32_t st = sb + buf * STG_F;
        const size_t g = ((size_t)b * SEQ + n0 + srow) * DMODEL + h * DK + (scb >> 1);
        const uint32_t ro = (uint32_t)srow * ROWB + scb;
        cpa16(st + SK_H + ro,      KHg + g);
        cpa16(st + SK_H + ro + 16, KHg + g + 8);
        cpa16(st + SK_L + ro,      KLg + g);
        cpa16(st + SK_L + ro + 16, KLg + g + 8);
        cpa16(st + SV_H + ro,      VHg + g);
        cpa16(st + SV_H + ro + 16, VHg + g + 8);
        cpa16(st + SV_L + ro,      VLg + g);
        cpa16(st + SV_L + ro + 16, VLg + g + 8);
    };

    float o[8][4];
#pragma unroll
    for (int nt = 0; nt < 8; nt++)
#pragma unroll
        for (int r = 0; r < 4; r++) o[nt][r] = 0.f;
    float m0 = -3.0e38f, m1 = -3.0e38f, l0 = 0.f, l1 = 0.f;

    const int r0 = bm + wid * 16 + (lane >> 2);
    const uint32_t* mrow0 = &mpk[((size_t)b * SEQ + r0) * (SEQ / 32)];
    const uint32_t* mrow1 = mrow0 + 8 * (SEQ / 32);

    const int b_row = (lane & 7) + ((lane >> 4) & 1) * 8;
    const uint32_t b_off = (uint32_t)((lane >> 3) & 1) * 16;
    const int v_row = (lane & 7) + ((lane >> 3) & 1) * 8;
    const uint32_t v_off = (uint32_t)((lane >> 4) & 1) * 16;
    const int colbase = (lane & 3) * 2;

    issue(0, 0);
    CPA_COMMIT();

    for (int c = 0; c < SEQ / 64; c++) {
        if (c + 1 < SEQ / 64) {
            issue((c + 1) & 1, (c + 1) * 64);
            CPA_COMMIT();
            CPA_WAIT1();
        } else {
            CPA_WAIT0();
        }
        __syncthreads();
        const uint32_t st = sb + (c & 1) * STG_F;

        float s[8][4];
#pragma unroll
        for (int nt = 0; nt < 8; nt++)
#pragma unroll
            for (int r = 0; r < 4; r++) s[nt][r] = 0.f;

#pragma unroll
        for (int ks = 0; ks < 4; ks++) {
#pragma unroll
            for (int nt2 = 0; nt2 < 4; nt2++) {
                uint32_t kh[4], kl[4];
                const uint32_t rb = (uint32_t)(b_row + nt2 * 16) * ROWB + (uint32_t)ks * 32 + b_off;
                LDMATRIX_X4(kh[0], kh[1], kh[2], kh[3], st + SK_H + rb);
                LDMATRIX_X4(kl[0], kl[1], kl[2], kl[3], st + SK_L + rb);
#pragma unroll
                for (int j = 0; j < 2; j++) {
                    const int nt = nt2 * 2 + j;
                    MMA16816(s[nt], qh[ks], kh[j * 2], kh[j * 2 + 1]);
                    MMA16816(s[nt], ql[ks], kh[j * 2], kh[j * 2 + 1]);
                    MMA16816(s[nt], qh[ks], kl[j * 2], kl[j * 2 + 1]);
                }
            }
        }

        {
            const uint64_t mk0 = (uint64_t)mrow0[c * 2] | ((uint64_t)mrow0[c * 2 + 1] << 32);
            const uint64_t mk1 = (uint64_t)mrow1[c * 2] | ((uint64_t)mrow1[c * 2 + 1] << 32);
#pragma unroll
            for (int nt = 0; nt < 8; nt++) {
                const int col = nt * 8 + colbase;
                s[nt][0] += ((mk0 >> col) & 1) ? -1e9f : 0.f;
                s[nt][1] += ((mk0 >> (col + 1)) & 1) ? -1e9f : 0.f;
                s[nt][2] += ((mk1 >> col) & 1) ? -1e9f : 0.f;
                s[nt][3] += ((mk1 >> (col + 1)) & 1) ? -1e9f : 0.f;
            }
        }

        float cm0 = -3.0e38f, cm1 = -3.0e38f;
#pragma unroll
        for (int nt = 0; nt < 8; nt++) {
            cm0 = fmaxf(cm0, fmaxf(s[nt][0], s[nt][1]));
            cm1 = fmaxf(cm1, fmaxf(s[nt][2], s[nt][3]));
        }
        cm0 = fmaxf(cm0, __shfl_xor_sync(0xffffffffu, cm0, 1));
        cm0 = fmaxf(cm0, __shfl_xor_sync(0xffffffffu, cm0, 2));
        cm1 = fmaxf(cm1, __shfl_xor_sync(0xffffffffu, cm1, 1));
        cm1 = fmaxf(cm1, __shfl_xor_sync(0xffffffffu, cm1, 2));

        const float mn0 = fmaxf(m0, cm0), mn1 = fmaxf(m1, cm1);
        const float sc0 = __expf(m0 - mn0), sc1 = __expf(m1 - mn1);
        l0 *= sc0; l1 *= sc1;
#pragma unroll
        for (int nt = 0; nt < 8; nt++) {
            o[nt][0] *= sc0; o[nt][1] *= sc0;
            o[nt][2] *= sc1; o[nt][3] *= sc1;
        }
        m0 = mn0; m1 = mn1;

        uint32_t aPh[4][4], aPl[4][4];
#pragma unroll
        for (int nt = 0; nt < 8; nt++) {
            float p0 = __expf(s[nt][0] - mn0);
            float p1 = __expf(s[nt][1] - mn0);
            float p2 = __expf(s[nt][2] - mn1);
            float p3 = __expf(s[nt][3] - mn1);
            l0 += p0 + p1; l1 += p2 + p3;
            const int t = nt >> 1, jj = (nt & 1) * 2;
            uint32_t hp01, lp01, hp23, lp23;
            split_pair(p0, p1, hp01, lp01);
            split_pair(p2, p3, hp23, lp23);
            aPh[t][jj] = hp01; aPh[t][jj + 1] = hp23;
            aPl[t][jj] = lp01; aPl[t][jj + 1] = lp23;
        }

#pragma unroll
        for (int t = 0; t < 4; t++) {
#pragma unroll
            for (int nt2 = 0; nt2 < 4; nt2++) {
                uint32_t vh[4], vl[4];
                const uint32_t rb = (uint32_t)(t * 16 + v_row) * ROWB + (uint32_t)nt2 * 32 + v_off;
                LDMATRIX_X4_T(vh[0], vh[1], vh[2], vh[3], st + SV_H + rb);
                LDMATRIX_X4_T(vl[0], vl[1], vl[2], vl[3], st + SV_L + rb);
#pragma unroll
                for (int j = 0; j < 2; j++) {
                    const int nt = nt2 * 2 + j;
                    MMA16816(o[nt], aPh[t], vh[j * 2], vh[j * 2 + 1]);
                    MMA16816(o[nt], aPl[t], vh[j * 2], vh[j * 2 + 1]);
                    MMA16816(o[nt], aPh[t], vl[j * 2], vl[j * 2 + 1]);
                }
            }
        }
        __syncthreads();
    }

    // ---- epilogue: write Ctx as hi/lo bf16 ----
    l0 += __shfl_xor_sync(0xffffffffu, l0, 1);
    l0 += __shfl_xor_sync(0xffffffffu, l0, 2);
    l1 += __shfl_xor_sync(0xffffffffu, l1, 1);
    l1 += __shfl_xor_sync(0xffffffffu, l1, 2);
    const float inv0 = 1.f / l0, inv1 = 1.f / l1;

    const int ecol = h * DK + (lane & 3) * 2;
    const size_t i0 = ((size_t)b * SEQ + r0) * DMODEL + ecol;
    const size_t i1 = ((size_t)b * SEQ + r0 + 8) * DMODEL + ecol;
#pragma unroll
    for (int nt = 0; nt < 8; nt++) {
        uint32_t hp, lp;
        split_pair(o[nt][0] * inv0, o[nt][1] * inv0, hp, lp);
        *(uint32_t*)&CtxH[i0 + nt * 8] = hp;
        *(uint32_t*)&CtxL[i0 + nt * 8] = lp;
        split_pair(o[nt][2] * inv1, o[nt][3] * inv1, hp, lp);
        *(uint32_t*)&CtxH[i1 + nt * 8] = hp;
        *(uint32_t*)&CtxL[i1 + nt * 8] = lp;
    }
}

// ---------------------------------------------------------------
extern "C" void kernel_launch(void* const* d_in, const int* in_sizes, int n_in,
                              void* d_out, int out_size) {
    const float*    q    = (const float*)d_in[0];
    const float*    k    = (const float*)d_in[1];
    const float*    v    = (const float*)d_in[2];
    const uint32_t* mask = (const uint32_t*)d_in[3];
    const float*    Wq   = (const float*)d_in[4];
    const float*    Wk   = (const float*)d_in[5];
    const float*    Wv   = (const float*)d_in[6];
    const float*    Wo   = (const float*)d_in[7];
    float* out = (float*)d_out;

    __nv_bfloat16 *AH, *AL, *BH, *BL, *WH, *WL;
    uint32_t* mpk;
    cudaGetSymbolAddress((void**)&AH, g_AH);
    cudaGetSymbolAddress((void**)&AL, g_AL);
    cudaGetSymbolAddress((void**)&BH, g_BH);
    cudaGetSymbolAddress((void**)&BL, g_BL);
    cudaGetSymbolAddress((void**)&WH, g_WH);
    cudaGetSymbolAddress((void**)&WL, g_WL);
    cudaGetSymbolAddress((void**)&mpk, g_mpk);

    cudaFuncSetAttribute(gemm_pipe, cudaFuncAttributeMaxDynamicSharedMemorySize, GEMM_SMEM);
    cudaFuncSetAttribute(flash_mma, cudaFuncAttributeMaxDynamicSharedMemorySize, FLASH_SMEM);

    const size_t AD = (size_t)GM * DMODEL;

    dim3 gpa(GM * DMODEL / 4 / 256, 3);
    presplit_a<<<gpa, 256>>>(q, k, v, AH, AL);
    dim3 gpw(DD / 4 / 256, 4);
    presplit_w<<<gpw, 256>>>(Wq, Wk, Wv, Wo, WH, WL);
    mask_pack<<<1024, 256>>>(mask, mpk);

    // QKV projections -> hi/lo bf16 directly (Q pre-scaled via Wq)
    dim3 gqkv(DMODEL / 256, 3 * GM / 128);
    gemm_pipe<<<gqkv, 256, GEMM_SMEM>>>(AH, AL, WH, WL, nullptr, BH, BL, 0);

    dim3 ga(SEQ / 128, NHEADS, BATCH);
    flash_mma<<<ga, 256, FLASH_SMEM>>>(BH, BL, BH + AD, BL + AD, BH + 2 * AD, BL + 2 * AD,
                                       mpk, AH, AL);   // Ctx -> AH/AL (first AD)

    // output projection (fp32 out)
    dim3 go(DMODEL / 256, GM / 128);
    gemm_pipe<<<go, 256, GEMM_SMEM>>>(AH, AL, WH + 3 * DD, WL + 3 * DD, out, nullptr, nullptr, 1);
}

// round 17
// speedup vs baseline: 3.2722x; 1.0256x over previous
#include <cuda_runtime.h>
#include <cuda_bf16.h>
#include <cstdint>

#define BATCH  2
#define SEQ    2048
#define DMODEL 1024
#define NHEADS 16
#define DK     64
#define GM     (BATCH * SEQ)
#define DD     (DMODEL * DMODEL)

// ---------------- scratch (no cudaMalloc allowed) ----------------
__device__ __nv_bfloat16 g_AH[(size_t)3 * GM * DMODEL];
__device__ __nv_bfloat16 g_AL[(size_t)3 * GM * DMODEL];
__device__ __nv_bfloat16 g_BH[(size_t)3 * GM * DMODEL];
__device__ __nv_bfloat16 g_BL[(size_t)3 * GM * DMODEL];
__device__ __nv_bfloat16 g_WH[(size_t)4 * DD];
__device__ __nv_bfloat16 g_WL[(size_t)4 * DD];
__device__ uint32_t g_mpk[(size_t)BATCH * SEQ * (SEQ / 32)];

// ======================= common helpers =======================
#define LDMATRIX_X4(r0, r1, r2, r3, addr)                                   \
    asm volatile("ldmatrix.sync.aligned.m8n8.x4.shared.b16 {%0,%1,%2,%3}, [%4];" \
                 : "=r"(r0), "=r"(r1), "=r"(r2), "=r"(r3) : "r"(addr))

#define LDMATRIX_X4_T(r0, r1, r2, r3, addr)                                 \
    asm volatile("ldmatrix.sync.aligned.m8n8.x4.trans.shared.b16 {%0,%1,%2,%3}, [%4];" \
                 : "=r"(r0), "=r"(r1), "=r"(r2), "=r"(r3) : "r"(addr))

#define MMA16816(d, a, b0, b1)                                              \
    asm volatile("mma.sync.aligned.m16n8k16.row.col.f32.bf16.bf16.f32 "     \
                 "{%0,%1,%2,%3}, {%4,%5,%6,%7}, {%8,%9}, {%0,%1,%2,%3};"    \
                 : "+f"((d)[0]), "+f"((d)[1]), "+f"((d)[2]), "+f"((d)[3])   \
                 : "r"((a)[0]), "r"((a)[1]), "r"((a)[2]), "r"((a)[3]),      \
                   "r"(b0), "r"(b1))

__device__ __forceinline__ uint32_t smem_u32(const void* p) {
    uint32_t a;
    asm("{ .reg .u64 t; cvta.to.shared.u64 t, %1; cvt.u32.u64 %0, t; }" : "=r"(a) : "l"(p));
    return a;
}

__device__ __forceinline__ void cpa16(uint32_t saddr, const void* g) {
    asm volatile("cp.async.cg.shared.global [%0], [%1], 16;" :: "r"(saddr), "l"(g));
}
#define CPA_COMMIT() asm volatile("cp.async.commit_group;" ::: "memory")
#define CPA_WAIT1()  asm volatile("cp.async.wait_group 1;" ::: "memory")
#define CPA_WAIT0()  asm volatile("cp.async.wait_group 0;" ::: "memory")

__device__ __forceinline__ void split4(float4 v, uint2& h, uint2& l) {
    __nv_bfloat16 hx = __float2bfloat16(v.x), hy = __float2bfloat16(v.y);
    __nv_bfloat16 hz = __float2bfloat16(v.z), hw = __float2bfloat16(v.w);
    __nv_bfloat16 lx = __float2bfloat16(v.x - __bfloat162float(hx));
    __nv_bfloat16 ly = __float2bfloat16(v.y - __bfloat162float(hy));
    __nv_bfloat16 lz = __float2bfloat16(v.z - __bfloat162float(hz));
    __nv_bfloat16 lw = __float2bfloat16(v.w - __bfloat162float(hw));
    __nv_bfloat162 h0 = __halves2bfloat162(hx, hy), h1 = __halves2bfloat162(hz, hw);
    __nv_bfloat162 l0 = __halves2bfloat162(lx, ly), l1 = __halves2bfloat162(lz, lw);
    h.x = *(uint32_t*)&h0; h.y = *(uint32_t*)&h1;
    l.x = *(uint32_t*)&l0; l.y = *(uint32_t*)&l1;
}

__device__ __forceinline__ uint32_t pack2(float a, float b) {
    uint32_t r;
    asm("cvt.rn.bf16x2.f32 %0, %1, %2;" : "=r"(r) : "f"(b), "f"(a));
    return r;
}

__device__ __forceinline__ void split_pair(float x, float y, uint32_t& hp, uint32_t& lp) {
    hp = pack2(x, y);
    __nv_bfloat162 hb = *(__nv_bfloat162*)&hp;
    lp = pack2(x - __bfloat162float(hb.x), y - __bfloat162float(hb.y));
}

// ======================= presplit kernels =======================
__global__ __launch_bounds__(256)
void presplit_a(const float* __restrict__ a0, const float* __restrict__ a1,
                const float* __restrict__ a2,
                __nv_bfloat16* __restrict__ hi, __nv_bfloat16* __restrict__ lo) {
    const int t = blockIdx.y;
    const float* src = (t == 0) ? a0 : (t == 1) ? a1 : a2;
    const size_t base = (size_t)t * (GM * DMODEL / 4);
    const size_t i = base + blockIdx.x * blockDim.x + threadIdx.x;
    float4 v = ((const float4*)src)[i - base];
    uint2 h, l;
    split4(v, h, l);
    ((uint2*)hi)[i] = h;
    ((uint2*)lo)[i] = l;
}

__global__ __launch_bounds__(256)
void presplit_w(const float* __restrict__ w0, const float* __restrict__ w1,
                const float* __restrict__ w2, const float* __restrict__ w3,
                __nv_bfloat16* __restrict__ hi, __nv_bfloat16* __restrict__ lo) {
    const int t = blockIdx.y;
    const float* src = (t == 0) ? w0 : (t == 1) ? w1 : (t == 2) ? w2 : w3;
    const float sc = (t == 0) ? 0.125f : 1.0f;
    const size_t base = (size_t)t * (DD / 4);
    const size_t i = base + blockIdx.x * blockDim.x + threadIdx.x;
    float4 v = ((const float4*)src)[i - base];
    v.x *= sc; v.y *= sc; v.z *= sc; v.w *= sc;
    uint2 h, l;
    split4(v, h, l);
    ((uint2*)hi)[i] = h;
    ((uint2*)lo)[i] = l;
}

// ======================= 3-stage pipelined hi/lo mma GEMM =======================
#define ROWS   80
#define ST_AH  0
#define ST_AL  10240
#define ST_BH  20480
#define ST_BL  40960
#define STAGE  61440
#define GEMM_SMEM (3 * STAGE)   // 184320

__global__ __launch_bounds__(256, 1)
void gemm_pipe(const __nv_bfloat16* __restrict__ Ah, const __nv_bfloat16* __restrict__ Al,
               const __nv_bfloat16* __restrict__ Wh, const __nv_bfloat16* __restrict__ Wl,
               float* __restrict__ C, __nv_bfloat16* __restrict__ CH,
               __nv_bfloat16* __restrict__ CL, int wantf32) {
    extern __shared__ __align__(16) char smem[];
    constexpr int K = DMODEL, N = DMODEL, NC = K / 32;

    const int tid = threadIdx.x;
    const int lane = tid & 31, wid = tid >> 5;
    const int warp_m = wid >> 2;
    const int warp_n = wid & 3;
    const int bm = blockIdx.y * 128;
    const int bn = blockIdx.x * 256;
    const int third = blockIdx.y >> 5;
    const __nv_bfloat16* WhS = Wh + (size_t)third * DD;
    const __nv_bfloat16* WlS = Wl + (size_t)third * DD;
    const uint32_t sb = smem_u32(smem);

    const int lrow = tid >> 2;
    const int lc = (tid & 3) * 16;

    auto issue = [&](int buf, int k0) {
        const uint32_t st = sb + buf * STAGE;
#pragma unroll
        for (int j = 0; j < 2; j++) {
            const int row = lrow + j * 64;
            const size_t g = (size_t)(bm + row) * K + k0 + (lc >> 1);
            cpa16(st + ST_AH + row * ROWS + lc, Ah + g);
            cpa16(st + ST_AL + row * ROWS + lc, Al + g);
        }
#pragma unroll
        for (int j = 0; j < 4; j++) {
            const int row = lrow + j * 64;
            const size_t g = (size_t)(bn + row) * K + k0 + (lc >> 1);
            cpa16(st + ST_BH + row * ROWS + lc, WhS + g);
            cpa16(st + ST_BL + row * ROWS + lc, WlS + g);
        }
    };

    float acc[4][8][4];
#pragma unroll
    for (int mt = 0; mt < 4; mt++)
#pragma unroll
        for (int nt = 0; nt < 8; nt++)
#pragma unroll
            for (int r = 0; r < 4; r++) acc[mt][nt][r] = 0.f;

    const int a_row = warp_m * 64 + (lane & 15);
    const uint32_t a_half = (uint32_t)(lane >> 4) * 16;
    const int b_row = warp_n * 64 + (lane & 7) + ((lane >> 4) & 1) * 8;
    const uint32_t b_half = (uint32_t)((lane >> 3) & 1) * 16;

    issue(0, 0);
    CPA_COMMIT();
    issue(1, 32);
    CPA_COMMIT();

    int buf = 0, nbuf = 2;
    for (int c = 0; c < NC; c++) {
        if (c == NC - 1) { CPA_WAIT0(); } else { CPA_WAIT1(); }
        __syncthreads();
        if (c + 2 < NC) {
            issue(nbuf, (c + 2) * 32);
            CPA_COMMIT();
        }

        const uint32_t st = sb + buf * STAGE;
#pragma unroll
        for (int ks = 0; ks < 2; ks++) {
            const uint32_t koff = (uint32_t)ks * 32;
            uint32_t ah[4][4], al[4][4];
#pragma unroll
            for (int mt = 0; mt < 4; mt++) {
                const uint32_t ra = (uint32_t)(a_row + mt * 16) * ROWS + koff + a_half;
                LDMATRIX_X4(ah[mt][0], ah[mt][1], ah[mt][2], ah[mt][3], st + ST_AH + ra);
                LDMATRIX_X4(al[mt][0], al[mt][1], al[mt][2], al[mt][3], st + ST_AL + ra);
            }
#pragma unroll
            for (int nt2 = 0; nt2 < 4; nt2++) {
                uint32_t bh[4], bl[4];
                const uint32_t rb = (uint32_t)(b_row + nt2 * 16) * ROWS + koff + b_half;
                LDMATRIX_X4(bh[0], bh[1], bh[2], bh[3], st + ST_BH + rb);
                LDMATRIX_X4(bl[0], bl[1], bl[2], bl[3], st + ST_BL + rb);
#pragma unroll
                for (int j = 0; j < 2; j++) {
                    const int nt = nt2 * 2 + j;
#pragma unroll
                    for (int mt = 0; mt < 4; mt++) {
                        MMA16816(acc[mt][nt], ah[mt], bh[j * 2], bh[j * 2 + 1]);
                        MMA16816(acc[mt][nt], al[mt], bh[j * 2], bh[j * 2 + 1]);
                        MMA16816(acc[mt][nt], ah[mt], bl[j * 2], bl[j * 2 + 1]);
                    }
                }
            }
        }
        buf = (buf == 2) ? 0 : buf + 1;
        nbuf = (nbuf == 2) ? 0 : nbuf + 1;
    }

    const int erow = bm + warp_m * 64 + (lane >> 2);
    const int ecol = bn + warp_n * 64 + (lane & 3) * 2;
    if (wantf32) {
#pragma unroll
        for (int mt = 0; mt < 4; mt++)
#pragma unroll
            for (int nt = 0; nt < 8; nt++) {
                float* c0 = &C[(size_t)(erow + mt * 16) * N + ecol + nt * 8];
                float* c1 = &C[(size_t)(erow + mt * 16 + 8) * N + ecol + nt * 8];
                *(float2*)c0 = make_float2(acc[mt][nt][0], acc[mt][nt][1]);
                *(float2*)c1 = make_float2(acc[mt][nt][2], acc[mt][nt][3]);
            }
    } else {
#pragma unroll
        for (int mt = 0; mt < 4; mt++)
#pragma unroll
            for (int nt = 0; nt < 8; nt++) {
                const size_t i0 = (size_t)(erow + mt * 16) * N + ecol + nt * 8;
                const size_t i1 = (size_t)(erow + mt * 16 + 8) * N + ecol + nt * 8;
                uint32_t hp, lp;
                split_pair(acc[mt][nt][0], acc[mt][nt][1], hp, lp);
                *(uint32_t*)&CH[i0] = hp; *(uint32_t*)&CL[i0] = lp;
                split_pair(acc[mt][nt][2], acc[mt][nt][3], hp, lp);
                *(uint32_t*)&CH[i1] = hp; *(uint32_t*)&CL[i1] = lp;
            }
    }
}

// ======================= mask bit-pack (validated R7) =======================
__global__ __launch_bounds__(256)
void mask_pack(const uint32_t* __restrict__ m, uint32_t* __restrict__ out) {
    const int gwarp = (blockIdx.x * blockDim.x + threadIdx.x) >> 5;
    const int lane = threadIdx.x & 31;
    const uint32_t* base = m + (size_t)gwarp * 1024;
    uint32_t my = 0;
#pragma unroll 4
    for (int g = 0; g < 32; g++) {
        uint32_t v = base[g * 32 + lane];
        uint32_t bal = __ballot_sync(0xffffffffu, v != 0);
        if (lane == g) my = bal;
    }
    out[(size_t)gwarp * 32 + lane] = my;
}

// ======================= tensor-core flash attention (3-stage) =============
#define ROWB   144
#define SK_H   0
#define SK_L   9216
#define SV_H   18432
#define SV_L   27648
#define STG_F  36864
#define FLASH_SMEM (3 * STG_F)   // 110592
#define AT_QH  0
#define AT_QL  18432

__global__ __launch_bounds__(256)
void flash_mma(const __nv_bfloat16* __restrict__ QHg, const __nv_bfloat16* __restrict__ QLg,
               const __nv_bfloat16* __restrict__ KHg, const __nv_bfloat16* __restrict__ KLg,
               const __nv_bfloat16* __restrict__ VHg, const __nv_bfloat16* __restrict__ VLg,
               const uint32_t* __restrict__ mpk,
               __nv_bfloat16* __restrict__ CtxH, __nv_bfloat16* __restrict__ CtxL) {
    extern __shared__ __align__(16) char smem[];
    const int b = blockIdx.z, h = blockIdx.y;
    const int tid = threadIdx.x, lane = tid & 31, wid = tid >> 5;
    const int bm = blockIdx.x * 128;
    const uint32_t sb = smem_u32(smem);
    constexpr int NC = SEQ / 64;

    // ---- stage Q hi/lo via cp.async into stage-0 area ----
    {
        const int qrow = tid >> 1;
        const uint32_t qco = (uint32_t)(tid & 1) * 64;
        const size_t gq = ((size_t)b * SEQ + bm + qrow) * DMODEL + h * DK + (qco >> 1);
        const uint32_t ro = (uint32_t)qrow * ROWB + qco;
#pragma unroll
        for (int i = 0; i < 4; i++) {
            cpa16(sb + AT_QH + ro + i * 16, QHg + gq + i * 8);
            cpa16(sb + AT_QL + ro + i * 16, QLg + gq + i * 8);
        }
    }
    CPA_COMMIT();
    CPA_WAIT0();
    __syncthreads();

    uint32_t qh[4][4], ql[4][4];
    {
        const int a_row = wid * 16 + (lane & 15);
        const uint32_t a_off = (uint32_t)(lane >> 4) * 16;
#pragma unroll
        for (int ks = 0; ks < 4; ks++) {
            const uint32_t ra = (uint32_t)a_row * ROWB + (uint32_t)ks * 32 + a_off;
            LDMATRIX_X4(qh[ks][0], qh[ks][1], qh[ks][2], qh[ks][3], sb + AT_QH + ra);
            LDMATRIX_X4(ql[ks][0], ql[ks][1], ql[ks][2], ql[ks][3], sb + AT_QL + ra);
        }
    }
    __syncthreads();   // Q consumed before pipeline reuses stage 0

    const int srow = tid >> 2;
    const int scb = (tid & 3) * 32;
    auto issue = [&](int buf, int n0) {
        const uint32_t st = sb + buf * STG_F;
        const size_t g = ((size_t)b * SEQ + n0 + srow) * DMODEL + h * DK + (scb >> 1);
        const uint32_t ro = (uint32_t)srow * ROWB + scb;
        cpa16(st + SK_H + ro,      KHg + g);
        cpa16(st + SK_H + ro + 16, KHg + g + 8);
        cpa16(st + SK_L + ro,      KLg + g);
        cpa16(st + SK_L + ro + 16, KLg + g + 8);
        cpa16(st + SV_H + ro,      VHg + g);
        cpa16(st + SV_H + ro + 16, VHg + g + 8);
        cpa16(st + SV_L + ro,      VLg + g);
        cpa16(st + SV_L + ro + 16, VLg + g + 8);
    };

    float o[8][4];
#pragma unroll
    for (int nt = 0; nt < 8; nt++)
#pragma unroll
        for (int r = 0; r < 4; r++) o[nt][r] = 0.f;
    float m0 = -3.0e38f, m1 = -3.0e38f, l0 = 0.f, l1 = 0.f;

    const int r0 = bm + wid * 16 + (lane >> 2);
    const uint32_t* mrow0 = &mpk[((size_t)b * SEQ + r0) * (SEQ / 32)];
    const uint32_t* mrow1 = mrow0 + 8 * (SEQ / 32);

    const int b_row = (lane & 7) + ((lane >> 4) & 1) * 8;
    const uint32_t b_off = (uint32_t)((lane >> 3) & 1) * 16;
    const int v_row = (lane & 7) + ((lane >> 3) & 1) * 8;
    const uint32_t v_off = (uint32_t)((lane >> 4) & 1) * 16;
    const int colbase = (lane & 3) * 2;

    issue(0, 0);
    CPA_COMMIT();
    issue(1, 64);
    CPA_COMMIT();

    int buf = 0, nbuf = 2;
    for (int c = 0; c < NC; c++) {
        if (c == NC - 1) { CPA_WAIT0(); } else { CPA_WAIT1(); }
        __syncthreads();
        if (c + 2 < NC) {
            issue(nbuf, (c + 2) * 64);
            CPA_COMMIT();
        }
        const uint32_t st = sb + buf * STG_F;

        float s[8][4];
#pragma unroll
        for (int nt = 0; nt < 8; nt++)
#pragma unroll
            for (int r = 0; r < 4; r++) s[nt][r] = 0.f;

#pragma unroll
        for (int ks = 0; ks < 4; ks++) {
#pragma unroll
            for (int nt2 = 0; nt2 < 4; nt2++) {
                uint32_t kh[4], kl[4];
                const uint32_t rb = (uint32_t)(b_row + nt2 * 16) * ROWB + (uint32_t)ks * 32 + b_off;
                LDMATRIX_X4(kh[0], kh[1], kh[2], kh[3], st + SK_H + rb);
                LDMATRIX_X4(kl[0], kl[1], kl[2], kl[3], st + SK_L + rb);
#pragma unroll
                for (int j = 0; j < 2; j++) {
                    const int nt = nt2 * 2 + j;
                    MMA16816(s[nt], qh[ks], kh[j * 2], kh[j * 2 + 1]);
                    MMA16816(s[nt], ql[ks], kh[j * 2], kh[j * 2 + 1]);
                    MMA16816(s[nt], qh[ks], kl[j * 2], kl[j * 2 + 1]);
                }
            }
        }

        {
            const uint64_t mk0 = (uint64_t)mrow0[c * 2] | ((uint64_t)mrow0[c * 2 + 1] << 32);
            const uint64_t mk1 = (uint64_t)mrow1[c * 2] | ((uint64_t)mrow1[c * 2 + 1] << 32);
#pragma unroll
            for (int nt = 0; nt < 8; nt++) {
                const int col = nt * 8 + colbase;
                s[nt][0] += ((mk0 >> col) & 1) ? -1e9f : 0.f;
                s[nt][1] += ((mk0 >> (col + 1)) & 1) ? -1e9f : 0.f;
                s[nt][2] += ((mk1 >> col) & 1) ? -1e9f : 0.f;
                s[nt][3] += ((mk1 >> (col + 1)) & 1) ? -1e9f : 0.f;
            }
        }

        float cm0 = -3.0e38f, cm1 = -3.0e38f;
#pragma unroll
        for (int nt = 0; nt < 8; nt++) {
            cm0 = fmaxf(cm0, fmaxf(s[nt][0], s[nt][1]));
            cm1 = fmaxf(cm1, fmaxf(s[nt][2], s[nt][3]));
        }
        cm0 = fmaxf(cm0, __shfl_xor_sync(0xffffffffu, cm0, 1));
        cm0 = fmaxf(cm0, __shfl_xor_sync(0xffffffffu, cm0, 2));
        cm1 = fmaxf(cm1, __shfl_xor_sync(0xffffffffu, cm1, 1));
        cm1 = fmaxf(cm1, __shfl_xor_sync(0xffffffffu, cm1, 2));

        const float mn0 = fmaxf(m0, cm0), mn1 = fmaxf(m1, cm1);
        const float sc0 = __expf(m0 - mn0), sc1 = __expf(m1 - mn1);
        l0 *= sc0; l1 *= sc1;
#pragma unroll
        for (int nt = 0; nt < 8; nt++) {
            o[nt][0] *= sc0; o[nt][1] *= sc0;
            o[nt][2] *= sc1; o[nt][3] *= sc1;
        }
        m0 = mn0; m1 = mn1;

        uint32_t aPh[4][4], aPl[4][4];
#pragma unroll
        for (int nt = 0; nt < 8; nt++) {
            float p0 = __expf(s[nt][0] - mn0);
            float p1 = __expf(s[nt][1] - mn0);
            float p2 = __expf(s[nt][2] - mn1);
            float p3 = __expf(s[nt][3] - mn1);
            l0 += p0 + p1; l1 += p2 + p3;
            const int t = nt >> 1, jj = (nt & 1) * 2;
            uint32_t hp01, lp01, hp23, lp23;
            split_pair(p0, p1, hp01, lp01);
            split_pair(p2, p3, hp23, lp23);
            aPh[t][jj] = hp01; aPh[t][jj + 1] = hp23;
            aPl[t][jj] = lp01; aPl[t][jj + 1] = lp23;
        }

#pragma unroll
        for (int t = 0; t < 4; t++) {
#pragma unroll
            for (int nt2 = 0; nt2 < 4; nt2++) {
                uint32_t vh[4], vl[4];
                const uint32_t rb = (uint32_t)(t * 16 + v_row) * ROWB + (uint32_t)nt2 * 32 + v_off;
                LDMATRIX_X4_T(vh[0], vh[1], vh[2], vh[3], st + SV_H + rb);
                LDMATRIX_X4_T(vl[0], vl[1], vl[2], vl[3], st + SV_L + rb);
#pragma unroll
                for (int j = 0; j < 2; j++) {
                    const int nt = nt2 * 2 + j;
                    MMA16816(o[nt], aPh[t], vh[j * 2], vh[j * 2 + 1]);
                    MMA16816(o[nt], aPl[t], vh[j * 2], vh[j * 2 + 1]);
                    MMA16816(o[nt], aPh[t], vl[j * 2], vl[j * 2 + 1]);
                }
            }
        }
        buf = (buf == 2) ? 0 : buf + 1;
        nbuf = (nbuf == 2) ? 0 : nbuf + 1;
    }

    // ---- epilogue: write Ctx as hi/lo bf16 ----
    l0 += __shfl_xor_sync(0xffffffffu, l0, 1);
    l0 += __shfl_xor_sync(0xffffffffu, l0, 2);
    l1 += __shfl_xor_sync(0xffffffffu, l1, 1);
    l1 += __shfl_xor_sync(0xffffffffu, l1, 2);
    const float inv0 = 1.f / l0, inv1 = 1.f / l1;

    const int ecol = h * DK + (lane & 3) * 2;
    const size_t i0 = ((size_t)b * SEQ + r0) * DMODEL + ecol;
    const size_t i1 = ((size_t)b * SEQ + r0 + 8) * DMODEL + ecol;
#pragma unroll
    for (int nt = 0; nt < 8; nt++) {
        uint32_t hp, lp;
        split_pair(o[nt][0] * inv0, o[nt][1] * inv0, hp, lp);
        *(uint32_t*)&CtxH[i0 + nt * 8] = hp;
        *(uint32_t*)&CtxL[i0 + nt * 8] = lp;
        split_pair(o[nt][2] * inv1, o[nt][3] * inv1, hp, lp);
        *(uint32_t*)&CtxH[i1 + nt * 8] = hp;
        *(uint32_t*)&CtxL[i1 + nt * 8] = lp;
    }
}

// ---------------------------------------------------------------
extern "C" void kernel_launch(void* const* d_in, const int* in_sizes, int n_in,
                              void* d_out, int out_size) {
    const float*    q    = (const float*)d_in[0];
    const float*    k    = (const float*)d_in[1];
    const float*    v    = (const float*)d_in[2];
    const uint32_t* mask = (const uint32_t*)d_in[3];
    const float*    Wq   = (const float*)d_in[4];
    const float*    Wk   = (const float*)d_in[5];
    const float*    Wv   = (const float*)d_in[6];
    const float*    Wo   = (const float*)d_in[7];
    float* out = (float*)d_out;

    __nv_bfloat16 *AH, *AL, *BH, *BL, *WH, *WL;
    uint32_t* mpk;
    cudaGetSymbolAddress((void**)&AH, g_AH);
    cudaGetSymbolAddress((void**)&AL, g_AL);
    cudaGetSymbolAddress((void**)&BH, g_BH);
    cudaGetSymbolAddress((void**)&BL, g_BL);
    cudaGetSymbolAddress((void**)&WH, g_WH);
    cudaGetSymbolAddress((void**)&WL, g_WL);
    cudaGetSymbolAddress((void**)&mpk, g_mpk);

    cudaFuncSetAttribute(gemm_pipe, cudaFuncAttributeMaxDynamicSharedMemorySize, GEMM_SMEM);
    cudaFuncSetAttribute(flash_mma, cudaFuncAttributeMaxDynamicSharedMemorySize, FLASH_SMEM);

    const size_t AD = (size_t)GM * DMODEL;

    dim3 gpa(GM * DMODEL / 4 / 256, 3);
    presplit_a<<<gpa, 256>>>(q, k, v, AH, AL);
    dim3 gpw(DD / 4 / 256, 4);
    presplit_w<<<gpw, 256>>>(Wq, Wk, Wv, Wo, WH, WL);
    mask_pack<<<1024, 256>>>(mask, mpk);

    dim3 gqkv(DMODEL / 256, 3 * GM / 128);
    gemm_pipe<<<gqkv, 256, GEMM_SMEM>>>(AH, AL, WH, WL, nullptr, BH, BL, 0);

    dim3 ga(SEQ / 128, NHEADS, BATCH);
    flash_mma<<<ga, 256, FLASH_SMEM>>>(BH, BL, BH + AD, BL + AD, BH + 2 * AD, BL + 2 * AD,
                                       mpk, AH, AL);

    dim3 go(DMODEL / 256, GM / 128);
    gemm_pipe<<<go, 256, GEMM_SMEM>>>(AH, AL, WH + 3 * DD, WL + 3 * DD, out, nullptr, nullptr, 1);
}